// round 5
// baseline (speedup 1.0000x reference)
#include <cuda_runtime.h>
#include <cuda_bf16.h>
#include <math.h>

#define TT    2048   // tokens (B*S)
#define DD    1024   // model dim
#define HH    16     // heads
#define HDIM  64     // head dim
#define NEXP  16     // experts
#define TOPK  2
#define EDIM  512    // expert dim
#define DSH   2048   // shared expert dim
#define QKV3  3072

// ---------------- scratch (device globals; no allocations) ----------------
constexpr size_t SZ_XN  = (size_t)TT * DD;
constexpr size_t OFF_XN  = 0;
constexpr size_t OFF_QKV = OFF_XN  + SZ_XN;                      // [T,3D]
constexpr size_t OFF_AO  = OFF_QKV + (size_t)TT * QKV3;          // attn out [T,D]
constexpr size_t OFF_XFI = OFF_AO  + SZ_XN;                      // x_ffn_input
constexpr size_t OFF_XFN = OFF_XFI + SZ_XN;                      // x_ffn
constexpr size_t OFF_SC  = OFF_XFN + SZ_XN;                      // scores [T,2]
constexpr size_t OFF_G   = OFF_SC  + (size_t)TT * TOPK;          // g [T*2, ED]
constexpr size_t OFF_YP  = OFF_G   + (size_t)TT * TOPK * EDIM;   // y_partial [T*2, D]
constexpr size_t OFF_YC  = OFF_YP  + (size_t)TT * TOPK * DD;     // y combined
constexpr size_t OFF_UP  = OFF_YC  + SZ_XN;                      // shared up [T, 2*DS]
constexpr size_t OFF_GT  = OFF_UP  + (size_t)TT * 2 * DSH;       // gated [T, DS]
constexpr size_t OFF_YS  = OFF_GT  + (size_t)TT * DSH;           // shared down [T,D]
constexpr size_t TOTF    = OFF_YS  + SZ_XN;

__device__ float g_bufF[TOTF];

constexpr int IOFF_CNT  = 0;       // counts[16]
constexpr int IOFF_OFFS = 16;      // offsets[17]
constexpr int IOFF_CUR  = 33;      // cursor[16]
constexpr int IOFF_PERM = 64;      // perm_token[4096]
constexpr int IOFF_SLOT = 64 + TT*TOPK; // slotpos[4096]
constexpr int TOTI      = 64 + 2*TT*TOPK;
__device__ int g_bufI[TOTI];

// ---------------- rmsnorm ----------------
__global__ void rmsnorm_kernel(const float* __restrict__ x, const float* __restrict__ w,
                               float* __restrict__ o) {
    int t = blockIdx.x;
    const float* xr = x + (size_t)t * DD;
    float v[4]; float s = 0.f;
    #pragma unroll
    for (int i = 0; i < 4; i++) { v[i] = xr[threadIdx.x + i*256]; s += v[i]*v[i]; }
    __shared__ float red[8];
    #pragma unroll
    for (int off = 16; off > 0; off >>= 1) s += __shfl_xor_sync(0xffffffffu, s, off);
    if ((threadIdx.x & 31) == 0) red[threadIdx.x >> 5] = s;
    __syncthreads();
    if (threadIdx.x == 0) {
        float tot = 0.f;
        #pragma unroll
        for (int i = 0; i < 8; i++) tot += red[i];
        red[0] = tot;
    }
    __syncthreads();
    float sc = rsqrtf(red[0] / (float)DD + 1e-5f);
    #pragma unroll
    for (int i = 0; i < 4; i++) {
        int d = threadIdx.x + i*256;
        o[(size_t)t*DD + d] = v[i] * sc * w[d];
    }
}

// ---------------- generic NT GEMM: C[M,N] = A[M,K] @ B[N,K]^T (+R) -------
__global__ void gemm_nt_kernel(const float* __restrict__ A, const float* __restrict__ B,
                               const float* __restrict__ R, float* __restrict__ C,
                               int M, int N, int K) {
    __shared__ float As[16][65];
    __shared__ float Bs[16][65];
    const int tid = threadIdx.x;
    const int tx4 = (tid & 15) * 4, ty4 = (tid >> 4) * 4;
    const int row0 = blockIdx.y * 64, col0 = blockIdx.x * 64;
    const int lm = tid >> 2, lk = (tid & 3) << 2;
    const bool aval = (row0 + lm) < M;
    const float* Ap = A + (size_t)(row0 + lm) * K + lk;
    const float* Bp = B + (size_t)(col0 + lm) * K + lk;
    float acc[4][4] = {};
    for (int k0 = 0; k0 < K; k0 += 16) {
        float4 av = aval ? *(const float4*)(Ap + k0) : make_float4(0,0,0,0);
        float4 bv = *(const float4*)(Bp + k0);
        As[lk+0][lm]=av.x; As[lk+1][lm]=av.y; As[lk+2][lm]=av.z; As[lk+3][lm]=av.w;
        Bs[lk+0][lm]=bv.x; Bs[lk+1][lm]=bv.y; Bs[lk+2][lm]=bv.z; Bs[lk+3][lm]=bv.w;
        __syncthreads();
        #pragma unroll
        for (int kk = 0; kk < 16; kk++) {
            float a0=As[kk][ty4+0], a1=As[kk][ty4+1], a2=As[kk][ty4+2], a3=As[kk][ty4+3];
            float b0=Bs[kk][tx4+0], b1=Bs[kk][tx4+1], b2=Bs[kk][tx4+2], b3=Bs[kk][tx4+3];
            acc[0][0]+=a0*b0; acc[0][1]+=a0*b1; acc[0][2]+=a0*b2; acc[0][3]+=a0*b3;
            acc[1][0]+=a1*b0; acc[1][1]+=a1*b1; acc[1][2]+=a1*b2; acc[1][3]+=a1*b3;
            acc[2][0]+=a2*b0; acc[2][1]+=a2*b1; acc[2][2]+=a2*b2; acc[2][3]+=a2*b3;
            acc[3][0]+=a3*b0; acc[3][1]+=a3*b1; acc[3][2]+=a3*b2; acc[3][3]+=a3*b3;
        }
        __syncthreads();
    }
    #pragma unroll
    for (int i = 0; i < 4; i++) {
        int r = row0 + ty4 + i;
        if (r >= M) continue;
        #pragma unroll
        for (int j = 0; j < 4; j++) {
            size_t idx = (size_t)r * N + col0 + tx4 + j;
            float v = acc[i][j];
            if (R) v += R[idx];
            C[idx] = v;
        }
    }
}

// ---------------- RoPE (in-place on q,k within qkv buffer) ----------------
__global__ void rope_kernel(float* __restrict__ qkv) {
    int idx = blockIdx.x * blockDim.x + threadIdx.x;
    const int total = 2 * TT * HH * 32;
    if (idx >= total) return;
    int which = idx / (TT * HH * 32);             // 0=q, 1=k
    int rem   = idx % (TT * HH * 32);
    int t = rem / (HH * 32);
    int r2 = rem % (HH * 32);
    int h = r2 >> 5, i = r2 & 31;
    size_t base = (size_t)t * QKV3 + (size_t)which * DD + h * HDIM;
    // match reference f32 rounding: inv_freq rounded to f32, pos*inv in f32, trig accurate
    float invf = (float)exp(-9.210340371976184 * ((double)i / 32.0));
    float fr = (float)t * invf;
    float c = (float)cos((double)fr);
    float s = (float)sin((double)fr);
    float x1 = qkv[base + i];
    float x2 = qkv[base + 32 + i];
    qkv[base + i]      =  x1 * c + x2 * s;
    qkv[base + 32 + i] = -x1 * s + x2 * c;
}

// ---------------- flash attention (64q x 64k tiles, fp32) ----------------
__global__ void attn_kernel(const float* __restrict__ qkv, float* __restrict__ o) {
    extern __shared__ float sm[];
    float* Qs = sm;              // [64][65] transposed: Qs[d][q]
    float* Ks = Qs + 64*65;      // Ks[d][k]
    float* Vs = Ks + 64*65;      // Vs[k][d]
    float* Ps = Vs + 64*65;      // Ps[k][q]
    float* mrow = Ps + 64*65;
    float* lrow = mrow + 64;
    float* arow = lrow + 64;
    int qb = blockIdx.x, h = blockIdx.y;
    int tid = threadIdx.x;
    int tx4 = (tid & 15) * 4, ty4 = (tid >> 4) * 4;

    { // load Q transposed
        int qi = tid >> 2, d0 = (tid & 3) << 2;
        #pragma unroll
        for (int dp = 0; dp < 64; dp += 16) {
            float4 v = *(const float4*)(qkv + (size_t)(qb*64+qi)*QKV3 + h*HDIM + dp + d0);
            Qs[(dp+d0+0)*65+qi]=v.x; Qs[(dp+d0+1)*65+qi]=v.y;
            Qs[(dp+d0+2)*65+qi]=v.z; Qs[(dp+d0+3)*65+qi]=v.w;
        }
    }
    if (tid < 64) { mrow[tid] = -INFINITY; lrow[tid] = 0.f; }
    float acc[4][4] = {};

    for (int kb = 0; kb <= qb; kb++) {
        __syncthreads();
        { // K transposed
            int kj = tid >> 2, d0 = (tid & 3) << 2;
            #pragma unroll
            for (int dp = 0; dp < 64; dp += 16) {
                float4 v = *(const float4*)(qkv + (size_t)(kb*64+kj)*QKV3 + DD + h*HDIM + dp + d0);
                Ks[(dp+d0+0)*65+kj]=v.x; Ks[(dp+d0+1)*65+kj]=v.y;
                Ks[(dp+d0+2)*65+kj]=v.z; Ks[(dp+d0+3)*65+kj]=v.w;
            }
            int kj2 = tid >> 4, d2 = (tid & 15) << 2;
            #pragma unroll
            for (int kp = 0; kp < 64; kp += 16) {
                float4 v = *(const float4*)(qkv + (size_t)(kb*64+kp+kj2)*QKV3 + 2*DD + h*HDIM + d2);
                Vs[(kp+kj2)*65 + d2+0]=v.x; Vs[(kp+kj2)*65 + d2+1]=v.y;
                Vs[(kp+kj2)*65 + d2+2]=v.z; Vs[(kp+kj2)*65 + d2+3]=v.w;
            }
        }
        __syncthreads();
        float s[4][4] = {};
        #pragma unroll
        for (int d = 0; d < 64; d++) {
            float a0=Qs[d*65+ty4+0], a1=Qs[d*65+ty4+1], a2=Qs[d*65+ty4+2], a3=Qs[d*65+ty4+3];
            float b0=Ks[d*65+tx4+0], b1=Ks[d*65+tx4+1], b2=Ks[d*65+tx4+2], b3=Ks[d*65+tx4+3];
            s[0][0]+=a0*b0; s[0][1]+=a0*b1; s[0][2]+=a0*b2; s[0][3]+=a0*b3;
            s[1][0]+=a1*b0; s[1][1]+=a1*b1; s[1][2]+=a1*b2; s[1][3]+=a1*b3;
            s[2][0]+=a2*b0; s[2][1]+=a2*b1; s[2][2]+=a2*b2; s[2][3]+=a2*b3;
            s[3][0]+=a3*b0; s[3][1]+=a3*b1; s[3][2]+=a3*b2; s[3][3]+=a3*b3;
        }
        #pragma unroll
        for (int i = 0; i < 4; i++) {
            int qg = qb*64 + ty4 + i;
            #pragma unroll
            for (int j = 0; j < 4; j++) {
                int kg = kb*64 + tx4 + j;
                float v = s[i][j] * 0.125f;
                if (kg > qg) v = -1e30f;
                Ps[(tx4+j)*65 + ty4 + i] = v;
            }
        }
        __syncthreads();
        { // online softmax, 4 threads per row
            int r = tid >> 2, cb = (tid & 3) * 16;
            float vmax = -INFINITY;
            #pragma unroll
            for (int c = 0; c < 16; c++) vmax = fmaxf(vmax, Ps[(cb+c)*65 + r]);
            vmax = fmaxf(vmax, __shfl_xor_sync(0xffffffffu, vmax, 1));
            vmax = fmaxf(vmax, __shfl_xor_sync(0xffffffffu, vmax, 2));
            float mold = mrow[r];
            float mnew = fmaxf(mold, vmax);
            float psum = 0.f;
            #pragma unroll
            for (int c = 0; c < 16; c++) {
                float p = __expf(Ps[(cb+c)*65 + r] - mnew);
                Ps[(cb+c)*65 + r] = p;
                psum += p;
            }
            psum += __shfl_xor_sync(0xffffffffu, psum, 1);
            psum += __shfl_xor_sync(0xffffffffu, psum, 2);
            float alpha = __expf(mold - mnew);
            if ((tid & 3) == 0) { mrow[r] = mnew; lrow[r] = lrow[r]*alpha + psum; arow[r] = alpha; }
        }
        __syncthreads();
        float al[4];
        #pragma unroll
        for (int i = 0; i < 4; i++) al[i] = arow[ty4+i];
        #pragma unroll
        for (int i = 0; i < 4; i++)
            #pragma unroll
            for (int j = 0; j < 4; j++) acc[i][j] *= al[i];
        #pragma unroll
        for (int kj = 0; kj < 64; kj++) {
            float a0=Ps[kj*65+ty4+0], a1=Ps[kj*65+ty4+1], a2=Ps[kj*65+ty4+2], a3=Ps[kj*65+ty4+3];
            float b0=Vs[kj*65+tx4+0], b1=Vs[kj*65+tx4+1], b2=Vs[kj*65+tx4+2], b3=Vs[kj*65+tx4+3];
            acc[0][0]+=a0*b0; acc[0][1]+=a0*b1; acc[0][2]+=a0*b2; acc[0][3]+=a0*b3;
            acc[1][0]+=a1*b0; acc[1][1]+=a1*b1; acc[1][2]+=a1*b2; acc[1][3]+=a1*b3;
            acc[2][0]+=a2*b0; acc[2][1]+=a2*b1; acc[2][2]+=a2*b2; acc[2][3]+=a2*b3;
            acc[3][0]+=a3*b0; acc[3][1]+=a3*b1; acc[3][2]+=a3*b2; acc[3][3]+=a3*b3;
        }
    }
    float li[4];
    #pragma unroll
    for (int i = 0; i < 4; i++) li[i] = 1.f / lrow[ty4+i];
    #pragma unroll
    for (int i = 0; i < 4; i++)
        #pragma unroll
        for (int j = 0; j < 4; j++)
            o[(size_t)(qb*64+ty4+i)*DD + h*HDIM + tx4 + j] = acc[i][j] * li[i];
}

// ---------------- router ----------------
__global__ void router_kernel(const float* __restrict__ xffn, const float* __restrict__ mk,
                              const float* __restrict__ bias, const int* __restrict__ indices,
                              const float* __restrict__ values, float* __restrict__ scores) {
    int t = blockIdx.x;
    __shared__ float red[128 * NEXP];
    float partial[NEXP];
    #pragma unroll
    for (int e = 0; e < NEXP; e++) partial[e] = 0.f;
    for (int d = threadIdx.x; d < DD; d += 128) {
        float xv = xffn[(size_t)t*DD + d];
        const float* mrow = mk + (size_t)d * NEXP;
        #pragma unroll
        for (int e = 0; e < NEXP; e++) partial[e] += xv * mrow[e];
    }
    #pragma unroll
    for (int e = 0; e < NEXP; e++) red[threadIdx.x*NEXP + e] = partial[e];
    __syncthreads();
    for (int s = 64; s >= 1; s >>= 1) {
        if (threadIdx.x < s)
            #pragma unroll
            for (int e = 0; e < NEXP; e++)
                red[threadIdx.x*NEXP + e] += red[(threadIdx.x+s)*NEXP + e];
        __syncthreads();
    }
    if (threadIdx.x == 0) {
        int i0 = indices[t*2+0], i1 = indices[t*2+1];
        float v0 = values[t*2+0] + red[i0] + bias[i0];
        float v1 = values[t*2+1] + red[i1] + bias[i1];
        float m = fmaxf(v0, v1);
        float e0 = __expf(v0 - m), e1 = __expf(v1 - m);
        float inv = 1.f / (e0 + e1);
        scores[t*2+0] = e0 * inv;
        scores[t*2+1] = e1 * inv;
    }
}

// ---------------- routing build ----------------
__global__ void route_init(int* counts) { if (threadIdx.x < NEXP) counts[threadIdx.x] = 0; }
__global__ void route_count(const int* __restrict__ indices, int* counts) {
    int i = blockIdx.x * blockDim.x + threadIdx.x;
    if (i < TT*TOPK) atomicAdd(&counts[indices[i]], 1);
}
__global__ void route_scan(const int* __restrict__ counts, int* offsets, int* cursor) {
    if (threadIdx.x == 0) {
        int off = 0;
        for (int e = 0; e < NEXP; e++) { offsets[e] = off; cursor[e] = off; off += counts[e]; }
        offsets[NEXP] = off;
    }
}
__global__ void route_scatter(const int* __restrict__ indices, int* cursor,
                              int* __restrict__ perm, int* __restrict__ slotpos) {
    int i = blockIdx.x * blockDim.x + threadIdx.x;
    if (i < TT*TOPK) {
        int e = indices[i];
        int p = atomicAdd(&cursor[e], 1);
        perm[p] = i >> 1;        // token id
        slotpos[i] = p;
    }
}

// ---------------- expert up: g = silu(x@W1) * (x@W2), gathered rows -------
__global__ void expert_up_kernel(const float* __restrict__ xffn, const float* __restrict__ experts,
                                 const int* __restrict__ counts, const int* __restrict__ offsets,
                                 const int* __restrict__ perm, float* __restrict__ g) {
    int e = blockIdx.z;
    int M = counts[e];
    int row0 = blockIdx.y * 64;
    if (row0 >= M) return;
    int off = offsets[e];
    const float* B1 = experts + (size_t)e * DD * EDIM;
    const float* B2 = experts + ((size_t)NEXP + e) * DD * EDIM;
    __shared__ float As[16][65];
    __shared__ float B1s[16][64];
    __shared__ float B2s[16][64];
    const int tid = threadIdx.x;
    const int tx4 = (tid & 15) * 4, ty4 = (tid >> 4) * 4;
    const int lm = tid >> 2, lk = (tid & 3) << 2;  // A loader
    const int bk = tid >> 4, bn = (tid & 15) << 2; // B loader
    const int col0 = blockIdx.x * 64;
    int r = row0 + lm;
    bool aval = r < M;
    int tok = aval ? perm[off + r] : 0;
    const float* Ap = xffn + (size_t)tok * DD + lk;
    float acc1[4][4] = {}, acc2[4][4] = {};
    for (int k0 = 0; k0 < DD; k0 += 16) {
        float4 av = aval ? *(const float4*)(Ap + k0) : make_float4(0,0,0,0);
        As[lk+0][lm]=av.x; As[lk+1][lm]=av.y; As[lk+2][lm]=av.z; As[lk+3][lm]=av.w;
        float4 b1 = *(const float4*)(B1 + (size_t)(k0+bk)*EDIM + col0 + bn);
        float4 b2 = *(const float4*)(B2 + (size_t)(k0+bk)*EDIM + col0 + bn);
        *(float4*)&B1s[bk][bn] = b1;
        *(float4*)&B2s[bk][bn] = b2;
        __syncthreads();
        #pragma unroll
        for (int kk = 0; kk < 16; kk++) {
            float a0=As[kk][ty4+0], a1=As[kk][ty4+1], a2=As[kk][ty4+2], a3=As[kk][ty4+3];
            float c0=B1s[kk][tx4+0], c1=B1s[kk][tx4+1], c2=B1s[kk][tx4+2], c3=B1s[kk][tx4+3];
            float d0=B2s[kk][tx4+0], d1=B2s[kk][tx4+1], d2=B2s[kk][tx4+2], d3=B2s[kk][tx4+3];
            acc1[0][0]+=a0*c0; acc1[0][1]+=a0*c1; acc1[0][2]+=a0*c2; acc1[0][3]+=a0*c3;
            acc1[1][0]+=a1*c0; acc1[1][1]+=a1*c1; acc1[1][2]+=a1*c2; acc1[1][3]+=a1*c3;
            acc1[2][0]+=a2*c0; acc1[2][1]+=a2*c1; acc1[2][2]+=a2*c2; acc1[2][3]+=a2*c3;
            acc1[3][0]+=a3*c0; acc1[3][1]+=a3*c1; acc1[3][2]+=a3*c2; acc1[3][3]+=a3*c3;
            acc2[0][0]+=a0*d0; acc2[0][1]+=a0*d1; acc2[0][2]+=a0*d2; acc2[0][3]+=a0*d3;
            acc2[1][0]+=a1*d0; acc2[1][1]+=a1*d1; acc2[1][2]+=a1*d2; acc2[1][3]+=a1*d3;
            acc2[2][0]+=a2*d0; acc2[2][1]+=a2*d1; acc2[2][2]+=a2*d2; acc2[2][3]+=a2*d3;
            acc2[3][0]+=a3*d0; acc2[3][1]+=a3*d1; acc2[3][2]+=a3*d2; acc2[3][3]+=a3*d3;
        }
        __syncthreads();
    }
    #pragma unroll
    for (int i = 0; i < 4; i++) {
        int rr = row0 + ty4 + i;
        if (rr >= M) continue;
        #pragma unroll
        for (int j = 0; j < 4; j++) {
            float h1 = acc1[i][j], h2 = acc2[i][j];
            float sig = 1.f / (1.f + __expf(-h1));
            g[(size_t)(off + rr) * EDIM + col0 + tx4 + j] = h1 * sig * h2;
        }
    }
}

// ---------------- expert down: yp = g @ W3^T (batched per expert) --------
__global__ void expert_down_kernel(const float* __restrict__ gbuf, const float* __restrict__ experts,
                                   const int* __restrict__ counts, const int* __restrict__ offsets,
                                   float* __restrict__ yp) {
    int e = blockIdx.z;
    int M = counts[e];
    int row0 = blockIdx.y * 64;
    if (row0 >= M) return;
    int off = offsets[e];
    const float* A = gbuf + (size_t)off * EDIM;
    const float* B = experts + (2*(size_t)NEXP + e) * DD * EDIM;  // [D rows][ED cols] NT
    float* C = yp + (size_t)off * DD;
    __shared__ float As[16][65];
    __shared__ float Bs[16][65];
    const int tid = threadIdx.x;
    const int tx4 = (tid & 15) * 4, ty4 = (tid >> 4) * 4;
    const int lm = tid >> 2, lk = (tid & 3) << 2;
    const int col0 = blockIdx.x * 64;
    bool aval = (row0 + lm) < M;
    const float* Ap = A + (size_t)(row0 + lm) * EDIM + lk;
    const float* Bp = B + (size_t)(col0 + lm) * EDIM + lk;
    float acc[4][4] = {};
    for (int k0 = 0; k0 < EDIM; k0 += 16) {
        float4 av = aval ? *(const float4*)(Ap + k0) : make_float4(0,0,0,0);
        float4 bv = *(const float4*)(Bp + k0);
        As[lk+0][lm]=av.x; As[lk+1][lm]=av.y; As[lk+2][lm]=av.z; As[lk+3][lm]=av.w;
        Bs[lk+0][lm]=bv.x; Bs[lk+1][lm]=bv.y; Bs[lk+2][lm]=bv.z; Bs[lk+3][lm]=bv.w;
        __syncthreads();
        #pragma unroll
        for (int kk = 0; kk < 16; kk++) {
            float a0=As[kk][ty4+0], a1=As[kk][ty4+1], a2=As[kk][ty4+2], a3=As[kk][ty4+3];
            float b0=Bs[kk][tx4+0], b1=Bs[kk][tx4+1], b2=Bs[kk][tx4+2], b3=Bs[kk][tx4+3];
            acc[0][0]+=a0*b0; acc[0][1]+=a0*b1; acc[0][2]+=a0*b2; acc[0][3]+=a0*b3;
            acc[1][0]+=a1*b0; acc[1][1]+=a1*b1; acc[1][2]+=a1*b2; acc[1][3]+=a1*b3;
            acc[2][0]+=a2*b0; acc[2][1]+=a2*b1; acc[2][2]+=a2*b2; acc[2][3]+=a2*b3;
            acc[3][0]+=a3*b0; acc[3][1]+=a3*b1; acc[3][2]+=a3*b2; acc[3][3]+=a3*b3;
        }
        __syncthreads();
    }
    #pragma unroll
    for (int i = 0; i < 4; i++) {
        int r = row0 + ty4 + i;
        if (r >= M) continue;
        #pragma unroll
        for (int j = 0; j < 4; j++)
            C[(size_t)r * DD + col0 + tx4 + j] = acc[i][j];
    }
}

// ---------------- combine experts (scores * yp) * coeff -------------------
__global__ void combine_kernel(const float* __restrict__ yp, const float* __restrict__ scores,
                               const int* __restrict__ slotpos, const float* __restrict__ coeff,
                               float* __restrict__ ycomb) {
    int t = blockIdx.x;
    float s0 = scores[t*2+0], s1 = scores[t*2+1];
    int p0 = slotpos[t*2+0], p1 = slotpos[t*2+1];
    const float* r0 = yp + (size_t)p0 * DD;
    const float* r1 = yp + (size_t)p1 * DD;
    #pragma unroll
    for (int i = 0; i < 4; i++) {
        int d = threadIdx.x + i*256;
        ycomb[(size_t)t*DD + d] = (s0*r0[d] + s1*r1[d]) * coeff[d];
    }
}

// ---------------- shared expert gate ----------------
__global__ void gate_kernel(const float* __restrict__ up, float* __restrict__ gate) {
    int idx = blockIdx.x * blockDim.x + threadIdx.x;
    if (idx >= TT*DSH) return;
    int t = idx / DSH, j = idx % DSH;
    float a = up[(size_t)t*2*DSH + j];
    float b = up[(size_t)t*2*DSH + DSH + j];
    float sig = 1.f / (1.f + __expf(-a));
    gate[idx] = a * sig * b;
}

// ---------------- final: out = ycomb + rmsnorm(ysh)*w + x_ffn_input ------
__global__ void final_kernel(const float* __restrict__ ycomb, const float* __restrict__ ysh,
                             const float* __restrict__ shw, const float* __restrict__ xfi,
                             float* __restrict__ out) {
    int t = blockIdx.x;
    const float* yr = ysh + (size_t)t * DD;
    float v[4]; float s = 0.f;
    #pragma unroll
    for (int i = 0; i < 4; i++) { v[i] = yr[threadIdx.x + i*256]; s += v[i]*v[i]; }
    __shared__ float red[8];
    #pragma unroll
    for (int off = 16; off > 0; off >>= 1) s += __shfl_xor_sync(0xffffffffu, s, off);
    if ((threadIdx.x & 31) == 0) red[threadIdx.x >> 5] = s;
    __syncthreads();
    if (threadIdx.x == 0) {
        float tot = 0.f;
        #pragma unroll
        for (int i = 0; i < 8; i++) tot += red[i];
        red[0] = tot;
    }
    __syncthreads();
    float sc = rsqrtf(red[0] / (float)DD + 1e-5f);
    #pragma unroll
    for (int i = 0; i < 4; i++) {
        int d = threadIdx.x + i*256;
        size_t idx = (size_t)t*DD + d;
        out[idx] = ycomb[idx] + v[i]*sc*shw[d] + xfi[idx];
    }
}

// ---------------- launch ----------------
extern "C" void kernel_launch(void* const* d_in, const int* in_sizes, int n_in,
                              void* d_out, int out_size) {
    const float* x_input     = (const float*)d_in[0];
    const int*   indices     = (const int*)  d_in[1];
    const float* values      = (const float*)d_in[2];
    const float* attn_w      = (const float*)d_in[3];
    const float* attn_o_w    = (const float*)d_in[4];
    const float* attn_norm_w = (const float*)d_in[5];
    const float* ffn_norm_w  = (const float*)d_in[6];
    const float* ffn_experts = (const float*)d_in[7];
    const float* main_keys   = (const float*)d_in[8];
    const float* main_bias   = (const float*)d_in[9];
    const float* out_coeff   = (const float*)d_in[10];
    const float* ffn_up_w    = (const float*)d_in[11];
    const float* ffn_down_w  = (const float*)d_in[12];
    const float* shared_nw   = (const float*)d_in[13];
    float* out = (float*)d_out;

    float* bufF = nullptr; int* bufI = nullptr;
    cudaGetSymbolAddress((void**)&bufF, g_bufF);
    cudaGetSymbolAddress((void**)&bufI, g_bufI);

    float* xn   = bufF + OFF_XN;
    float* qkv  = bufF + OFF_QKV;
    float* ao   = bufF + OFF_AO;
    float* xfi  = bufF + OFF_XFI;
    float* xfn  = bufF + OFF_XFN;
    float* sc   = bufF + OFF_SC;
    float* gbuf = bufF + OFF_G;
    float* yp   = bufF + OFF_YP;
    float* yc   = bufF + OFF_YC;
    float* up   = bufF + OFF_UP;
    float* gt   = bufF + OFF_GT;
    float* ys   = bufF + OFF_YS;

    int* cnt  = bufI + IOFF_CNT;
    int* offs = bufI + IOFF_OFFS;
    int* cur  = bufI + IOFF_CUR;
    int* perm = bufI + IOFF_PERM;
    int* slot = bufI + IOFF_SLOT;

    const int ATTN_SMEM = (4*64*65 + 3*64) * sizeof(float);
    cudaFuncSetAttribute(attn_kernel, cudaFuncAttributeMaxDynamicSharedMemorySize, ATTN_SMEM);

    // 1. attention pre-norm
    rmsnorm_kernel<<<TT, 256>>>(x_input, attn_norm_w, xn);
    // 2. QKV
    gemm_nt_kernel<<<dim3(QKV3/64, TT/64), 256>>>(xn, attn_w, nullptr, qkv, TT, QKV3, DD);
    // 3. RoPE on q,k
    rope_kernel<<<(2*TT*HH*32 + 255)/256, 256>>>(qkv);
    // 4. attention
    attn_kernel<<<dim3(TT/64, HH), 256, ATTN_SMEM>>>(qkv, ao);
    // 5. O proj + residual
    gemm_nt_kernel<<<dim3(DD/64, TT/64), 256>>>(ao, attn_o_w, x_input, xfi, TT, DD, DD);
    // 6. ffn pre-norm
    rmsnorm_kernel<<<TT, 256>>>(xfi, ffn_norm_w, xfn);
    // 7. router scores
    router_kernel<<<TT, 128>>>(xfn, main_keys, main_bias, indices, values, sc);
    // 8. routing permutation
    route_init<<<1, 32>>>(cnt);
    route_count<<<(TT*TOPK + 255)/256, 256>>>(indices, cnt);
    route_scan<<<1, 32>>>(cnt, offs, cur);
    route_scatter<<<(TT*TOPK + 255)/256, 256>>>(indices, cur, perm, slot);
    // 9. expert up (dual GEMM + SiLU)
    expert_up_kernel<<<dim3(EDIM/64, (TT*TOPK)/64, NEXP), 256>>>(xfn, ffn_experts, cnt, offs, perm, gbuf);
    // 10. expert down
    expert_down_kernel<<<dim3(DD/64, (TT*TOPK)/64, NEXP), 256>>>(gbuf, ffn_experts, cnt, offs, yp);
    // 11. combine
    combine_kernel<<<TT, 256>>>(yp, sc, slot, out_coeff, yc);
    // 12. shared expert up
    gemm_nt_kernel<<<dim3(2*DSH/64, TT/64), 256>>>(xfn, ffn_up_w, nullptr, up, TT, 2*DSH, DD);
    // 13. gate
    gate_kernel<<<(TT*DSH + 255)/256, 256>>>(up, gt);
    // 14. shared expert down
    gemm_nt_kernel<<<dim3(DD/64, TT/64), 256>>>(gt, ffn_down_w, nullptr, ys, TT, DD, DSH);
    // 15. final combine
    final_kernel<<<TT, 256>>>(yc, ys, shared_nw, xfi, out);
}

// round 6
// speedup vs baseline: 2.1868x; 2.1868x over previous
#include <cuda_runtime.h>
#include <cuda_bf16.h>
#include <math.h>

#define TT    2048   // tokens (B*S)
#define DD    1024   // model dim
#define HH    16     // heads
#define HDIM  64     // head dim
#define NEXP  16     // experts
#define TOPK  2
#define EDIM  512    // expert dim
#define DSH   2048   // shared expert dim
#define QKV3  3072

// ---------------- scratch (device globals; no allocations) ----------------
constexpr size_t SZ_XN  = (size_t)TT * DD;
constexpr size_t OFF_XN  = 0;
constexpr size_t OFF_QKV = OFF_XN  + SZ_XN;
constexpr size_t OFF_AO  = OFF_QKV + (size_t)TT * QKV3;
constexpr size_t OFF_XFI = OFF_AO  + SZ_XN;
constexpr size_t OFF_XFN = OFF_XFI + SZ_XN;
constexpr size_t OFF_SC  = OFF_XFN + SZ_XN;
constexpr size_t OFF_G   = OFF_SC  + (size_t)TT * TOPK;
constexpr size_t OFF_YP  = OFF_G   + (size_t)TT * TOPK * EDIM;
constexpr size_t OFF_YC  = OFF_YP  + (size_t)TT * TOPK * DD;
constexpr size_t OFF_UP  = OFF_YC  + SZ_XN;
constexpr size_t OFF_GT  = OFF_UP  + (size_t)TT * 2 * DSH;
constexpr size_t OFF_YS  = OFF_GT  + (size_t)TT * DSH;
constexpr size_t TOTF    = OFF_YS  + SZ_XN;

__device__ float g_bufF[TOTF];

constexpr int IOFF_CNT  = 0;
constexpr int IOFF_OFFS = 16;
constexpr int IOFF_CUR  = 33;
constexpr int IOFF_PERM = 64;
constexpr int IOFF_SLOT = 64 + TT*TOPK;
constexpr int TOTI      = 64 + 2*TT*TOPK;
__device__ int g_bufI[TOTI];

// ---------------- tf32 mma helpers ----------------
__device__ __forceinline__ unsigned f2tf32(float x) {
    unsigned u; asm("cvt.rna.tf32.f32 %0, %1;" : "=r"(u) : "f"(x)); return u;
}
__device__ __forceinline__ void mma8(float* c, const unsigned* a, const unsigned* b) {
    asm volatile("mma.sync.aligned.m16n8k8.row.col.f32.tf32.tf32.f32 "
        "{%0,%1,%2,%3},{%4,%5,%6,%7},{%8,%9},{%0,%1,%2,%3};"
        : "+f"(c[0]), "+f"(c[1]), "+f"(c[2]), "+f"(c[3])
        : "r"(a[0]), "r"(a[1]), "r"(a[2]), "r"(a[3]), "r"(b[0]), "r"(b[1]));
}

// ---------------- rmsnorm ----------------
__global__ void rmsnorm_kernel(const float* __restrict__ x, const float* __restrict__ w,
                               float* __restrict__ o) {
    int t = blockIdx.x;
    const float* xr = x + (size_t)t * DD;
    float v[4]; float s = 0.f;
    #pragma unroll
    for (int i = 0; i < 4; i++) { v[i] = xr[threadIdx.x + i*256]; s += v[i]*v[i]; }
    __shared__ float red[8];
    #pragma unroll
    for (int off = 16; off > 0; off >>= 1) s += __shfl_xor_sync(0xffffffffu, s, off);
    if ((threadIdx.x & 31) == 0) red[threadIdx.x >> 5] = s;
    __syncthreads();
    if (threadIdx.x == 0) {
        float tot = 0.f;
        #pragma unroll
        for (int i = 0; i < 8; i++) tot += red[i];
        red[0] = tot;
    }
    __syncthreads();
    float sc = rsqrtf(red[0] / (float)DD + 1e-5f);
    #pragma unroll
    for (int i = 0; i < 4; i++) {
        int d = threadIdx.x + i*256;
        o[(size_t)t*DD + d] = v[i] * sc * w[d];
    }
}

// =============== tf32 NT GEMM: C[M,N] = A[M,K] @ B[N,K]^T (+R) ===========
// BM=128 BN=64 BK=32, 256 threads (8 warps: 4 along M x 2 along N).
struct SmemNT {
    unsigned As[128][36];
    unsigned Bs[64][36];
};

__device__ __forceinline__ void gemm_nt_body(
        SmemNT& s, const float* __restrict__ A, const float* __restrict__ B,
        const float* __restrict__ R, float* __restrict__ C,
        int M, int N, int K, int row0, int col0) {
    const int tid = threadIdx.x;
    const int lane = tid & 31, w = tid >> 5;
    const int g = lane >> 2, tg = lane & 3;
    const int wm = (w & 3) * 32, wn = (w >> 2) * 32;
    const int ar = tid >> 3, ac = (tid & 7) * 4;

    const float* Ap[4]; bool va[4];
    #pragma unroll
    for (int p = 0; p < 4; p++) {
        int r = row0 + p*32 + ar;
        va[p] = r < M;
        Ap[p] = A + (size_t)(va[p] ? r : 0) * K + ac;
    }
    const float* Bp[2];
    #pragma unroll
    for (int p = 0; p < 2; p++)
        Bp[p] = B + (size_t)(col0 + p*32 + ar) * K + ac;

    // initial tile
    #pragma unroll
    for (int p = 0; p < 4; p++) {
        float4 v = va[p] ? *(const float4*)(Ap[p]) : make_float4(0,0,0,0);
        s.As[p*32+ar][ac+0]=f2tf32(v.x); s.As[p*32+ar][ac+1]=f2tf32(v.y);
        s.As[p*32+ar][ac+2]=f2tf32(v.z); s.As[p*32+ar][ac+3]=f2tf32(v.w);
    }
    #pragma unroll
    for (int p = 0; p < 2; p++) {
        float4 v = *(const float4*)(Bp[p]);
        s.Bs[p*32+ar][ac+0]=f2tf32(v.x); s.Bs[p*32+ar][ac+1]=f2tf32(v.y);
        s.Bs[p*32+ar][ac+2]=f2tf32(v.z); s.Bs[p*32+ar][ac+3]=f2tf32(v.w);
    }
    __syncthreads();

    float acc[2][4][4] = {};
    float4 pa[4], pb[2];
    for (int k0 = 0; k0 < K; k0 += 32) {
        bool nxt = (k0 + 32) < K;
        if (nxt) {
            #pragma unroll
            for (int p = 0; p < 4; p++)
                pa[p] = va[p] ? *(const float4*)(Ap[p] + k0 + 32) : make_float4(0,0,0,0);
            #pragma unroll
            for (int p = 0; p < 2; p++)
                pb[p] = *(const float4*)(Bp[p] + k0 + 32);
        }
        #pragma unroll
        for (int ks = 0; ks < 4; ks++) {
            const int kb = ks*8;
            unsigned af[2][4], bf[4][2];
            #pragma unroll
            for (int i = 0; i < 2; i++) {
                af[i][0] = s.As[wm+i*16+g  ][kb+tg];
                af[i][1] = s.As[wm+i*16+8+g][kb+tg];
                af[i][2] = s.As[wm+i*16+g  ][kb+tg+4];
                af[i][3] = s.As[wm+i*16+8+g][kb+tg+4];
            }
            #pragma unroll
            for (int j = 0; j < 4; j++) {
                bf[j][0] = s.Bs[wn+j*8+g][kb+tg];
                bf[j][1] = s.Bs[wn+j*8+g][kb+tg+4];
            }
            #pragma unroll
            for (int i = 0; i < 2; i++)
                #pragma unroll
                for (int j = 0; j < 4; j++)
                    mma8(acc[i][j], af[i], bf[j]);
        }
        __syncthreads();
        if (nxt) {
            #pragma unroll
            for (int p = 0; p < 4; p++) {
                s.As[p*32+ar][ac+0]=f2tf32(pa[p].x); s.As[p*32+ar][ac+1]=f2tf32(pa[p].y);
                s.As[p*32+ar][ac+2]=f2tf32(pa[p].z); s.As[p*32+ar][ac+3]=f2tf32(pa[p].w);
            }
            #pragma unroll
            for (int p = 0; p < 2; p++) {
                s.Bs[p*32+ar][ac+0]=f2tf32(pb[p].x); s.Bs[p*32+ar][ac+1]=f2tf32(pb[p].y);
                s.Bs[p*32+ar][ac+2]=f2tf32(pb[p].z); s.Bs[p*32+ar][ac+3]=f2tf32(pb[p].w);
            }
            __syncthreads();
        }
    }

    #pragma unroll
    for (int i = 0; i < 2; i++) {
        #pragma unroll
        for (int j = 0; j < 4; j++) {
            int r0 = row0 + wm + i*16 + g;
            int cc = col0 + wn + j*8 + tg*2;
            if (r0 < M) {
                size_t x = (size_t)r0*N + cc;
                float v0 = acc[i][j][0], v1 = acc[i][j][1];
                if (R) { v0 += R[x]; v1 += R[x+1]; }
                C[x] = v0; C[x+1] = v1;
            }
            int r1 = r0 + 8;
            if (r1 < M) {
                size_t x = (size_t)r1*N + cc;
                float v2 = acc[i][j][2], v3 = acc[i][j][3];
                if (R) { v2 += R[x]; v3 += R[x+1]; }
                C[x] = v2; C[x+1] = v3;
            }
        }
    }
}

__global__ __launch_bounds__(256) void gemm_tf32_nt(
        const float* __restrict__ A, const float* __restrict__ B,
        const float* __restrict__ R, float* __restrict__ C, int M, int N, int K) {
    __shared__ SmemNT s;
    gemm_nt_body(s, A, B, R, C, M, N, K, blockIdx.y * 128, blockIdx.x * 64);
}

// ---------------- RoPE (in-place on q,k within qkv buffer) ----------------
__global__ void rope_kernel(float* __restrict__ qkv) {
    int idx = blockIdx.x * blockDim.x + threadIdx.x;
    const int total = 2 * TT * HH * 32;
    if (idx >= total) return;
    int which = idx / (TT * HH * 32);
    int rem   = idx % (TT * HH * 32);
    int t = rem / (HH * 32);
    int r2 = rem % (HH * 32);
    int h = r2 >> 5, i = r2 & 31;
    size_t base = (size_t)t * QKV3 + (size_t)which * DD + h * HDIM;
    float invf = (float)exp(-9.210340371976184 * ((double)i / 32.0));
    float fr = (float)t * invf;
    float c = (float)cos((double)fr);
    float s = (float)sin((double)fr);
    float x1 = qkv[base + i];
    float x2 = qkv[base + 32 + i];
    qkv[base + i]      =  x1 * c + x2 * s;
    qkv[base + 32 + i] = -x1 * s + x2 * c;
}

// ---------------- flash attention (64q x 64k tiles, fp32) ----------------
__global__ void attn_kernel(const float* __restrict__ qkv, float* __restrict__ o) {
    extern __shared__ float sm[];
    float* Qs = sm;
    float* Ks = Qs + 64*65;
    float* Vs = Ks + 64*65;
    float* Ps = Vs + 64*65;
    float* mrow = Ps + 64*65;
    float* lrow = mrow + 64;
    float* arow = lrow + 64;
    int qb = gridDim.x - 1 - blockIdx.x;   // heavy blocks first
    int h = blockIdx.y;
    int tid = threadIdx.x;
    int tx4 = (tid & 15) * 4, ty4 = (tid >> 4) * 4;

    {
        int qi = tid >> 2, d0 = (tid & 3) << 2;
        #pragma unroll
        for (int dp = 0; dp < 64; dp += 16) {
            float4 v = *(const float4*)(qkv + (size_t)(qb*64+qi)*QKV3 + h*HDIM + dp + d0);
            Qs[(dp+d0+0)*65+qi]=v.x; Qs[(dp+d0+1)*65+qi]=v.y;
            Qs[(dp+d0+2)*65+qi]=v.z; Qs[(dp+d0+3)*65+qi]=v.w;
        }
    }
    if (tid < 64) { mrow[tid] = -INFINITY; lrow[tid] = 0.f; }
    float acc[4][4] = {};

    for (int kb = 0; kb <= qb; kb++) {
        __syncthreads();
        {
            int kj = tid >> 2, d0 = (tid & 3) << 2;
            #pragma unroll
            for (int dp = 0; dp < 64; dp += 16) {
                float4 v = *(const float4*)(qkv + (size_t)(kb*64+kj)*QKV3 + DD + h*HDIM + dp + d0);
                Ks[(dp+d0+0)*65+kj]=v.x; Ks[(dp+d0+1)*65+kj]=v.y;
                Ks[(dp+d0+2)*65+kj]=v.z; Ks[(dp+d0+3)*65+kj]=v.w;
            }
            int kj2 = tid >> 4, d2 = (tid & 15) << 2;
            #pragma unroll
            for (int kp = 0; kp < 64; kp += 16) {
                float4 v = *(const float4*)(qkv + (size_t)(kb*64+kp+kj2)*QKV3 + 2*DD + h*HDIM + d2);
                Vs[(kp+kj2)*65 + d2+0]=v.x; Vs[(kp+kj2)*65 + d2+1]=v.y;
                Vs[(kp+kj2)*65 + d2+2]=v.z; Vs[(kp+kj2)*65 + d2+3]=v.w;
            }
        }
        __syncthreads();
        float s[4][4] = {};
        #pragma unroll
        for (int d = 0; d < 64; d++) {
            float a0=Qs[d*65+ty4+0], a1=Qs[d*65+ty4+1], a2=Qs[d*65+ty4+2], a3=Qs[d*65+ty4+3];
            float b0=Ks[d*65+tx4+0], b1=Ks[d*65+tx4+1], b2=Ks[d*65+tx4+2], b3=Ks[d*65+tx4+3];
            s[0][0]+=a0*b0; s[0][1]+=a0*b1; s[0][2]+=a0*b2; s[0][3]+=a0*b3;
            s[1][0]+=a1*b0; s[1][1]+=a1*b1; s[1][2]+=a1*b2; s[1][3]+=a1*b3;
            s[2][0]+=a2*b0; s[2][1]+=a2*b1; s[2][2]+=a2*b2; s[2][3]+=a2*b3;
            s[3][0]+=a3*b0; s[3][1]+=a3*b1; s[3][2]+=a3*b2; s[3][3]+=a3*b3;
        }
        #pragma unroll
        for (int i = 0; i < 4; i++) {
            int qg = qb*64 + ty4 + i;
            #pragma unroll
            for (int j = 0; j < 4; j++) {
                int kg = kb*64 + tx4 + j;
                float v = s[i][j] * 0.125f;
                if (kg > qg) v = -1e30f;
                Ps[(tx4+j)*65 + ty4 + i] = v;
            }
        }
        __syncthreads();
        {
            int r = tid >> 2, cb = (tid & 3) * 16;
            float vmax = -INFINITY;
            #pragma unroll
            for (int c = 0; c < 16; c++) vmax = fmaxf(vmax, Ps[(cb+c)*65 + r]);
            vmax = fmaxf(vmax, __shfl_xor_sync(0xffffffffu, vmax, 1));
            vmax = fmaxf(vmax, __shfl_xor_sync(0xffffffffu, vmax, 2));
            float mold = mrow[r];
            float mnew = fmaxf(mold, vmax);
            float psum = 0.f;
            #pragma unroll
            for (int c = 0; c < 16; c++) {
                float p = __expf(Ps[(cb+c)*65 + r] - mnew);
                Ps[(cb+c)*65 + r] = p;
                psum += p;
            }
            psum += __shfl_xor_sync(0xffffffffu, psum, 1);
            psum += __shfl_xor_sync(0xffffffffu, psum, 2);
            float alpha = __expf(mold - mnew);
            if ((tid & 3) == 0) { mrow[r] = mnew; lrow[r] = lrow[r]*alpha + psum; arow[r] = alpha; }
        }
        __syncthreads();
        float al[4];
        #pragma unroll
        for (int i = 0; i < 4; i++) al[i] = arow[ty4+i];
        #pragma unroll
        for (int i = 0; i < 4; i++)
            #pragma unroll
            for (int j = 0; j < 4; j++) acc[i][j] *= al[i];
        #pragma unroll
        for (int kj = 0; kj < 64; kj++) {
            float a0=Ps[kj*65+ty4+0], a1=Ps[kj*65+ty4+1], a2=Ps[kj*65+ty4+2], a3=Ps[kj*65+ty4+3];
            float b0=Vs[kj*65+tx4+0], b1=Vs[kj*65+tx4+1], b2=Vs[kj*65+tx4+2], b3=Vs[kj*65+tx4+3];
            acc[0][0]+=a0*b0; acc[0][1]+=a0*b1; acc[0][2]+=a0*b2; acc[0][3]+=a0*b3;
            acc[1][0]+=a1*b0; acc[1][1]+=a1*b1; acc[1][2]+=a1*b2; acc[1][3]+=a1*b3;
            acc[2][0]+=a2*b0; acc[2][1]+=a2*b1; acc[2][2]+=a2*b2; acc[2][3]+=a2*b3;
            acc[3][0]+=a3*b0; acc[3][1]+=a3*b1; acc[3][2]+=a3*b2; acc[3][3]+=a3*b3;
        }
    }
    float li[4];
    #pragma unroll
    for (int i = 0; i < 4; i++) li[i] = 1.f / lrow[ty4+i];
    #pragma unroll
    for (int i = 0; i < 4; i++)
        #pragma unroll
        for (int j = 0; j < 4; j++)
            o[(size_t)(qb*64+ty4+i)*DD + h*HDIM + tx4 + j] = acc[i][j] * li[i];
}

// ---------------- router ----------------
__global__ void router_kernel(const float* __restrict__ xffn, const float* __restrict__ mk,
                              const float* __restrict__ bias, const int* __restrict__ indices,
                              const float* __restrict__ values, float* __restrict__ scores) {
    int t = blockIdx.x;
    __shared__ float red[128 * NEXP];
    float partial[NEXP];
    #pragma unroll
    for (int e = 0; e < NEXP; e++) partial[e] = 0.f;
    for (int d = threadIdx.x; d < DD; d += 128) {
        float xv = xffn[(size_t)t*DD + d];
        const float* mrow = mk + (size_t)d * NEXP;
        #pragma unroll
        for (int e = 0; e < NEXP; e++) partial[e] += xv * mrow[e];
    }
    #pragma unroll
    for (int e = 0; e < NEXP; e++) red[threadIdx.x*NEXP + e] = partial[e];
    __syncthreads();
    for (int s = 64; s >= 1; s >>= 1) {
        if (threadIdx.x < s)
            #pragma unroll
            for (int e = 0; e < NEXP; e++)
                red[threadIdx.x*NEXP + e] += red[(threadIdx.x+s)*NEXP + e];
        __syncthreads();
    }
    if (threadIdx.x == 0) {
        int i0 = indices[t*2+0], i1 = indices[t*2+1];
        float v0 = values[t*2+0] + red[i0] + bias[i0];
        float v1 = values[t*2+1] + red[i1] + bias[i1];
        float m = fmaxf(v0, v1);
        float e0 = __expf(v0 - m), e1 = __expf(v1 - m);
        float inv = 1.f / (e0 + e1);
        scores[t*2+0] = e0 * inv;
        scores[t*2+1] = e1 * inv;
    }
}

// ---------------- routing build ----------------
__global__ void route_init(int* counts) { if (threadIdx.x < NEXP) counts[threadIdx.x] = 0; }
__global__ void route_count(const int* __restrict__ indices, int* counts) {
    int i = blockIdx.x * blockDim.x + threadIdx.x;
    if (i < TT*TOPK) atomicAdd(&counts[indices[i]], 1);
}
__global__ void route_scan(const int* __restrict__ counts, int* offsets, int* cursor) {
    if (threadIdx.x == 0) {
        int off = 0;
        for (int e = 0; e < NEXP; e++) { offsets[e] = off; cursor[e] = off; off += counts[e]; }
        offsets[NEXP] = off;
    }
}
__global__ void route_scatter(const int* __restrict__ indices, int* cursor,
                              int* __restrict__ perm, int* __restrict__ slotpos) {
    int i = blockIdx.x * blockDim.x + threadIdx.x;
    if (i < TT*TOPK) {
        int e = indices[i];
        int p = atomicAdd(&cursor[e], 1);
        perm[p] = i >> 1;
        slotpos[i] = p;
    }
}

// =============== expert up (tf32): g = silu(x@W1) * (x@W2), gathered A ====
// BM=64 BN=64 BK=32, 256 threads (8 warps: 2 along M x 4 along N).
// B global layout [K=D][N=ED] (TN). Bs stored [BK][BN+8] (stride 72).
__global__ __launch_bounds__(256) void expert_up_tf32(
        const float* __restrict__ xffn, const float* __restrict__ experts,
        const int* __restrict__ counts, const int* __restrict__ offsets,
        const int* __restrict__ perm, float* __restrict__ g_out) {
    const int e = blockIdx.z;
    const int M = counts[e];
    const int row0 = blockIdx.y * 64;
    if (row0 >= M) return;
    const int off = offsets[e];
    const float* B1 = experts + (size_t)e * DD * EDIM;
    const float* B2 = experts + ((size_t)NEXP + e) * DD * EDIM;
    const int col0 = blockIdx.x * 64;

    __shared__ unsigned As[64][36];
    __shared__ unsigned B1s[32][72];
    __shared__ unsigned B2s[32][72];

    const int tid = threadIdx.x;
    const int lane = tid & 31, w = tid >> 5;
    const int g = lane >> 2, tg = lane & 3;
    const int wm = (w & 1) * 32, wn = (w >> 1) * 16;
    const int ar = tid >> 3, ac = (tid & 7) * 4;     // A: 32 rows/pass, 2 passes
    const int bkr = tid >> 4, bnc = (tid & 15) * 4;  // B: 16 k-rows/pass, 2 passes

    const float* Ap[2]; bool va[2];
    #pragma unroll
    for (int p = 0; p < 2; p++) {
        int r = row0 + p*32 + ar;
        va[p] = r < M;
        int tok = va[p] ? perm[off + r] : 0;
        Ap[p] = xffn + (size_t)tok * DD + ac;
    }
    const float* B1p[2]; const float* B2p[2];
    #pragma unroll
    for (int p = 0; p < 2; p++) {
        B1p[p] = B1 + (size_t)(p*16 + bkr) * EDIM + col0 + bnc;
        B2p[p] = B2 + (size_t)(p*16 + bkr) * EDIM + col0 + bnc;
    }

    // initial tile
    #pragma unroll
    for (int p = 0; p < 2; p++) {
        float4 v = va[p] ? *(const float4*)(Ap[p]) : make_float4(0,0,0,0);
        As[p*32+ar][ac+0]=f2tf32(v.x); As[p*32+ar][ac+1]=f2tf32(v.y);
        As[p*32+ar][ac+2]=f2tf32(v.z); As[p*32+ar][ac+3]=f2tf32(v.w);
    }
    #pragma unroll
    for (int p = 0; p < 2; p++) {
        float4 v1 = *(const float4*)(B1p[p]);
        float4 v2 = *(const float4*)(B2p[p]);
        B1s[p*16+bkr][bnc+0]=f2tf32(v1.x); B1s[p*16+bkr][bnc+1]=f2tf32(v1.y);
        B1s[p*16+bkr][bnc+2]=f2tf32(v1.z); B1s[p*16+bkr][bnc+3]=f2tf32(v1.w);
        B2s[p*16+bkr][bnc+0]=f2tf32(v2.x); B2s[p*16+bkr][bnc+1]=f2tf32(v2.y);
        B2s[p*16+bkr][bnc+2]=f2tf32(v2.z); B2s[p*16+bkr][bnc+3]=f2tf32(v2.w);
    }
    __syncthreads();

    float acc1[2][2][4] = {}, acc2[2][2][4] = {};
    float4 pa[2], pb1[2], pb2[2];
    for (int k0 = 0; k0 < DD; k0 += 32) {
        bool nxt = (k0 + 32) < DD;
        if (nxt) {
            #pragma unroll
            for (int p = 0; p < 2; p++)
                pa[p] = va[p] ? *(const float4*)(Ap[p] + k0 + 32) : make_float4(0,0,0,0);
            #pragma unroll
            for (int p = 0; p < 2; p++) {
                pb1[p] = *(const float4*)(B1p[p] + (size_t)(k0 + 32) * EDIM);
                pb2[p] = *(const float4*)(B2p[p] + (size_t)(k0 + 32) * EDIM);
            }
        }
        #pragma unroll
        for (int ks = 0; ks < 4; ks++) {
            const int kb = ks*8;
            unsigned af[2][4], bf1[2][2], bf2[2][2];
            #pragma unroll
            for (int i = 0; i < 2; i++) {
                af[i][0] = As[wm+i*16+g  ][kb+tg];
                af[i][1] = As[wm+i*16+8+g][kb+tg];
                af[i][2] = As[wm+i*16+g  ][kb+tg+4];
                af[i][3] = As[wm+i*16+8+g][kb+tg+4];
            }
            #pragma unroll
            for (int j = 0; j < 2; j++) {
                bf1[j][0] = B1s[kb+tg  ][wn+j*8+g];
                bf1[j][1] = B1s[kb+tg+4][wn+j*8+g];
                bf2[j][0] = B2s[kb+tg  ][wn+j*8+g];
                bf2[j][1] = B2s[kb+tg+4][wn+j*8+g];
            }
            #pragma unroll
            for (int i = 0; i < 2; i++)
                #pragma unroll
                for (int j = 0; j < 2; j++) {
                    mma8(acc1[i][j], af[i], bf1[j]);
                    mma8(acc2[i][j], af[i], bf2[j]);
                }
        }
        __syncthreads();
        if (nxt) {
            #pragma unroll
            for (int p = 0; p < 2; p++) {
                As[p*32+ar][ac+0]=f2tf32(pa[p].x); As[p*32+ar][ac+1]=f2tf32(pa[p].y);
                As[p*32+ar][ac+2]=f2tf32(pa[p].z); As[p*32+ar][ac+3]=f2tf32(pa[p].w);
            }
            #pragma unroll
            for (int p = 0; p < 2; p++) {
                B1s[p*16+bkr][bnc+0]=f2tf32(pb1[p].x); B1s[p*16+bkr][bnc+1]=f2tf32(pb1[p].y);
                B1s[p*16+bkr][bnc+2]=f2tf32(pb1[p].z); B1s[p*16+bkr][bnc+3]=f2tf32(pb1[p].w);
                B2s[p*16+bkr][bnc+0]=f2tf32(pb2[p].x); B2s[p*16+bkr][bnc+1]=f2tf32(pb2[p].y);
                B2s[p*16+bkr][bnc+2]=f2tf32(pb2[p].z); B2s[p*16+bkr][bnc+3]=f2tf32(pb2[p].w);
            }
            __syncthreads();
        }
    }

    #pragma unroll
    for (int i = 0; i < 2; i++) {
        #pragma unroll
        for (int j = 0; j < 2; j++) {
            int r0 = row0 + wm + i*16 + g;
            int cc = col0 + wn + j*8 + tg*2;
            #pragma unroll
            for (int half = 0; half < 2; half++) {
                int r = r0 + half*8;
                if (r < M) {
                    float h1a = acc1[i][j][half*2+0], h2a = acc2[i][j][half*2+0];
                    float h1b = acc1[i][j][half*2+1], h2b = acc2[i][j][half*2+1];
                    float sa = 1.f / (1.f + __expf(-h1a));
                    float sb = 1.f / (1.f + __expf(-h1b));
                    size_t x = (size_t)(off + r) * EDIM + cc;
                    g_out[x]   = h1a * sa * h2a;
                    g_out[x+1] = h1b * sb * h2b;
                }
            }
        }
    }
}

// =============== expert down (tf32 NT): yp = g @ W3^T, per-expert slabs ===
__global__ __launch_bounds__(256) void expert_down_tf32(
        const float* __restrict__ gbuf, const float* __restrict__ experts,
        const int* __restrict__ counts, const int* __restrict__ offsets,
        float* __restrict__ yp) {
    const int e = blockIdx.z;
    const int M = counts[e];
    const int row0 = blockIdx.y * 128;
    if (row0 >= M) return;
    const int off = offsets[e];
    __shared__ SmemNT s;
    gemm_nt_body(s,
                 gbuf + (size_t)off * EDIM,
                 experts + (2*(size_t)NEXP + e) * DD * EDIM,
                 nullptr,
                 yp + (size_t)off * DD,
                 M, DD, EDIM, row0, blockIdx.x * 64);
}

// ---------------- combine experts (scores * yp) * coeff -------------------
__global__ void combine_kernel(const float* __restrict__ yp, const float* __restrict__ scores,
                               const int* __restrict__ slotpos, const float* __restrict__ coeff,
                               float* __restrict__ ycomb) {
    int t = blockIdx.x;
    float s0 = scores[t*2+0], s1 = scores[t*2+1];
    int p0 = slotpos[t*2+0], p1 = slotpos[t*2+1];
    const float* r0 = yp + (size_t)p0 * DD;
    const float* r1 = yp + (size_t)p1 * DD;
    #pragma unroll
    for (int i = 0; i < 4; i++) {
        int d = threadIdx.x + i*256;
        ycomb[(size_t)t*DD + d] = (s0*r0[d] + s1*r1[d]) * coeff[d];
    }
}

// ---------------- shared expert gate ----------------
__global__ void gate_kernel(const float* __restrict__ up, float* __restrict__ gate) {
    int idx = blockIdx.x * blockDim.x + threadIdx.x;
    if (idx >= TT*DSH) return;
    int t = idx / DSH, j = idx % DSH;
    float a = up[(size_t)t*2*DSH + j];
    float b = up[(size_t)t*2*DSH + DSH + j];
    float sig = 1.f / (1.f + __expf(-a));
    gate[idx] = a * sig * b;
}

// ---------------- final: out = ycomb + rmsnorm(ysh)*w + x_ffn_input ------
__global__ void final_kernel(const float* __restrict__ ycomb, const float* __restrict__ ysh,
                             const float* __restrict__ shw, const float* __restrict__ xfi,
                             float* __restrict__ out) {
    int t = blockIdx.x;
    const float* yr = ysh + (size_t)t * DD;
    float v[4]; float s = 0.f;
    #pragma unroll
    for (int i = 0; i < 4; i++) { v[i] = yr[threadIdx.x + i*256]; s += v[i]*v[i]; }
    __shared__ float red[8];
    #pragma unroll
    for (int off = 16; off > 0; off >>= 1) s += __shfl_xor_sync(0xffffffffu, s, off);
    if ((threadIdx.x & 31) == 0) red[threadIdx.x >> 5] = s;
    __syncthreads();
    if (threadIdx.x == 0) {
        float tot = 0.f;
        #pragma unroll
        for (int i = 0; i < 8; i++) tot += red[i];
        red[0] = tot;
    }
    __syncthreads();
    float sc = rsqrtf(red[0] / (float)DD + 1e-5f);
    #pragma unroll
    for (int i = 0; i < 4; i++) {
        int d = threadIdx.x + i*256;
        size_t idx = (size_t)t*DD + d;
        out[idx] = ycomb[idx] + v[i]*sc*shw[d] + xfi[idx];
    }
}

// ---------------- launch ----------------
extern "C" void kernel_launch(void* const* d_in, const int* in_sizes, int n_in,
                              void* d_out, int out_size) {
    const float* x_input     = (const float*)d_in[0];
    const int*   indices     = (const int*)  d_in[1];
    const float* values      = (const float*)d_in[2];
    const float* attn_w      = (const float*)d_in[3];
    const float* attn_o_w    = (const float*)d_in[4];
    const float* attn_norm_w = (const float*)d_in[5];
    const float* ffn_norm_w  = (const float*)d_in[6];
    const float* ffn_experts = (const float*)d_in[7];
    const float* main_keys   = (const float*)d_in[8];
    const float* main_bias   = (const float*)d_in[9];
    const float* out_coeff   = (const float*)d_in[10];
    const float* ffn_up_w    = (const float*)d_in[11];
    const float* ffn_down_w  = (const float*)d_in[12];
    const float* shared_nw   = (const float*)d_in[13];
    float* out = (float*)d_out;

    float* bufF = nullptr; int* bufI = nullptr;
    cudaGetSymbolAddress((void**)&bufF, g_bufF);
    cudaGetSymbolAddress((void**)&bufI, g_bufI);

    float* xn   = bufF + OFF_XN;
    float* qkv  = bufF + OFF_QKV;
    float* ao   = bufF + OFF_AO;
    float* xfi  = bufF + OFF_XFI;
    float* xfn  = bufF + OFF_XFN;
    float* sc   = bufF + OFF_SC;
    float* gbuf = bufF + OFF_G;
    float* yp   = bufF + OFF_YP;
    float* yc   = bufF + OFF_YC;
    float* up   = bufF + OFF_UP;
    float* gt   = bufF + OFF_GT;
    float* ys   = bufF + OFF_YS;

    int* cnt  = bufI + IOFF_CNT;
    int* offs = bufI + IOFF_OFFS;
    int* cur  = bufI + IOFF_CUR;
    int* perm = bufI + IOFF_PERM;
    int* slot = bufI + IOFF_SLOT;

    const int ATTN_SMEM = (4*64*65 + 3*64) * sizeof(float);
    cudaFuncSetAttribute(attn_kernel, cudaFuncAttributeMaxDynamicSharedMemorySize, ATTN_SMEM);

    // 1. attention pre-norm
    rmsnorm_kernel<<<TT, 256>>>(x_input, attn_norm_w, xn);
    // 2. QKV (tf32 tensor)
    gemm_tf32_nt<<<dim3(QKV3/64, TT/128), 256>>>(xn, attn_w, nullptr, qkv, TT, QKV3, DD);
    // 3. RoPE on q,k
    rope_kernel<<<(2*TT*HH*32 + 255)/256, 256>>>(qkv);
    // 4. attention
    attn_kernel<<<dim3(TT/64, HH), 256, ATTN_SMEM>>>(qkv, ao);
    // 5. O proj + residual (tf32)
    gemm_tf32_nt<<<dim3(DD/64, TT/128), 256>>>(ao, attn_o_w, x_input, xfi, TT, DD, DD);
    // 6. ffn pre-norm
    rmsnorm_kernel<<<TT, 256>>>(xfi, ffn_norm_w, xfn);
    // 7. router scores
    router_kernel<<<TT, 128>>>(xfn, main_keys, main_bias, indices, values, sc);
    // 8. routing permutation
    route_init<<<1, 32>>>(cnt);
    route_count<<<(TT*TOPK + 255)/256, 256>>>(indices, cnt);
    route_scan<<<1, 32>>>(cnt, offs, cur);
    route_scatter<<<(TT*TOPK + 255)/256, 256>>>(indices, cur, perm, slot);
    // 9. expert up (tf32 dual GEMM + SiLU)
    expert_up_tf32<<<dim3(EDIM/64, (TT*TOPK)/64, NEXP), 256>>>(xfn, ffn_experts, cnt, offs, perm, gbuf);
    // 10. expert down (tf32)
    expert_down_tf32<<<dim3(DD/64, (TT*TOPK)/128, NEXP), 256>>>(gbuf, ffn_experts, cnt, offs, yp);
    // 11. combine
    combine_kernel<<<TT, 256>>>(yp, sc, slot, out_coeff, yc);
    // 12. shared expert up (tf32)
    gemm_tf32_nt<<<dim3(2*DSH/64, TT/128), 256>>>(xfn, ffn_up_w, nullptr, up, TT, 2*DSH, DD);
    // 13. gate
    gate_kernel<<<(TT*DSH + 255)/256, 256>>>(up, gt);
    // 14. shared expert down (tf32)
    gemm_tf32_nt<<<dim3(DD/64, TT/128), 256>>>(gt, ffn_down_w, nullptr, ys, TT, DD, DSH);
    // 15. final combine
    final_kernel<<<TT, 256>>>(yc, ys, shared_nw, xfi, out);
}

// round 8
// speedup vs baseline: 2.6401x; 1.2073x over previous
#include <cuda_runtime.h>
#include <cuda_bf16.h>
#include <math.h>

#define TT    2048   // tokens (B*S)
#define DD    1024   // model dim
#define HH    16     // heads
#define HDIM  64     // head dim
#define NEXP  16     // experts
#define TOPK  2
#define EDIM  512    // expert dim
#define DSH   2048   // shared expert dim
#define QKV3  3072

// ---------------- scratch (device globals; no allocations) ----------------
constexpr size_t SZ_XN  = (size_t)TT * DD;
constexpr size_t OFF_XN  = 0;
constexpr size_t OFF_QKV = OFF_XN  + SZ_XN;
constexpr size_t OFF_AO  = OFF_QKV + (size_t)TT * QKV3;
constexpr size_t OFF_XFI = OFF_AO  + SZ_XN;
constexpr size_t OFF_XFN = OFF_XFI + SZ_XN;
constexpr size_t OFF_SC  = OFF_XFN + SZ_XN;
constexpr size_t OFF_G   = OFF_SC  + (size_t)TT * TOPK;
constexpr size_t OFF_YP  = OFF_G   + (size_t)TT * TOPK * EDIM;
constexpr size_t OFF_YC  = OFF_YP  + (size_t)TT * TOPK * DD;
constexpr size_t OFF_UP  = OFF_YC  + SZ_XN;
constexpr size_t OFF_GT  = OFF_UP  + (size_t)TT * 2 * DSH;
constexpr size_t OFF_YS  = OFF_GT  + (size_t)TT * DSH;
constexpr size_t TOTF    = OFF_YS  + SZ_XN;

__device__ float g_bufF[TOTF];

constexpr int IOFF_CNT  = 0;
constexpr int IOFF_OFFS = 16;
constexpr int IOFF_CUR  = 33;
constexpr int IOFF_PERM = 64;
constexpr int IOFF_SLOT = 64 + TT*TOPK;
constexpr int TOTI      = 64 + 2*TT*TOPK;
__device__ int g_bufI[TOTI];

// ---------------- tf32 mma helpers ----------------
__device__ __forceinline__ unsigned f2tf32(float x) {
    unsigned u; asm("cvt.rna.tf32.f32 %0, %1;" : "=r"(u) : "f"(x)); return u;
}
__device__ __forceinline__ void mma8(float* c, const unsigned* a, const unsigned* b) {
    asm volatile("mma.sync.aligned.m16n8k8.row.col.f32.tf32.tf32.f32 "
        "{%0,%1,%2,%3},{%4,%5,%6,%7},{%8,%9},{%0,%1,%2,%3};"
        : "+f"(c[0]), "+f"(c[1]), "+f"(c[2]), "+f"(c[3])
        : "r"(a[0]), "r"(a[1]), "r"(a[2]), "r"(a[3]), "r"(b[0]), "r"(b[1]));
}

// ---------------- rmsnorm ----------------
__global__ void rmsnorm_kernel(const float* __restrict__ x, const float* __restrict__ w,
                               float* __restrict__ o) {
    int t = blockIdx.x;
    const float* xr = x + (size_t)t * DD;
    float v[4]; float s = 0.f;
    #pragma unroll
    for (int i = 0; i < 4; i++) { v[i] = xr[threadIdx.x + i*256]; s += v[i]*v[i]; }
    __shared__ float red[8];
    #pragma unroll
    for (int off = 16; off > 0; off >>= 1) s += __shfl_xor_sync(0xffffffffu, s, off);
    if ((threadIdx.x & 31) == 0) red[threadIdx.x >> 5] = s;
    __syncthreads();
    if (threadIdx.x == 0) {
        float tot = 0.f;
        #pragma unroll
        for (int i = 0; i < 8; i++) tot += red[i];
        red[0] = tot;
    }
    __syncthreads();
    float sc = rsqrtf(red[0] / (float)DD + 1e-5f);
    #pragma unroll
    for (int i = 0; i < 4; i++) {
        int d = threadIdx.x + i*256;
        o[(size_t)t*DD + d] = v[i] * sc * w[d];
    }
}

// =============== tf32 NT GEMM: C[M,N] = A[M,K] @ B[N,K]^T (+R) ===========
// BM=128 BN=64 BK=32, 256 threads (8 warps: 4 along M x 2 along N).
struct SmemNT {
    unsigned As[128][36];
    unsigned Bs[64][36];
};

__device__ __forceinline__ void gemm_nt_body(
        SmemNT& s, const float* __restrict__ A, const float* __restrict__ B,
        const float* __restrict__ R, float* __restrict__ C,
        int M, int N, int K, int row0, int col0) {
    const int tid = threadIdx.x;
    const int lane = tid & 31, w = tid >> 5;
    const int g = lane >> 2, tg = lane & 3;
    const int wm = (w & 3) * 32, wn = (w >> 2) * 32;
    const int ar = tid >> 3, ac = (tid & 7) * 4;

    const float* Ap[4]; bool va[4];
    #pragma unroll
    for (int p = 0; p < 4; p++) {
        int r = row0 + p*32 + ar;
        va[p] = r < M;
        Ap[p] = A + (size_t)(va[p] ? r : 0) * K + ac;
    }
    const float* Bp[2];
    #pragma unroll
    for (int p = 0; p < 2; p++)
        Bp[p] = B + (size_t)(col0 + p*32 + ar) * K + ac;

    #pragma unroll
    for (int p = 0; p < 4; p++) {
        float4 v = va[p] ? *(const float4*)(Ap[p]) : make_float4(0,0,0,0);
        s.As[p*32+ar][ac+0]=f2tf32(v.x); s.As[p*32+ar][ac+1]=f2tf32(v.y);
        s.As[p*32+ar][ac+2]=f2tf32(v.z); s.As[p*32+ar][ac+3]=f2tf32(v.w);
    }
    #pragma unroll
    for (int p = 0; p < 2; p++) {
        float4 v = *(const float4*)(Bp[p]);
        s.Bs[p*32+ar][ac+0]=f2tf32(v.x); s.Bs[p*32+ar][ac+1]=f2tf32(v.y);
        s.Bs[p*32+ar][ac+2]=f2tf32(v.z); s.Bs[p*32+ar][ac+3]=f2tf32(v.w);
    }
    __syncthreads();

    float acc[2][4][4] = {};
    float4 pa[4], pb[2];
    for (int k0 = 0; k0 < K; k0 += 32) {
        bool nxt = (k0 + 32) < K;
        if (nxt) {
            #pragma unroll
            for (int p = 0; p < 4; p++)
                pa[p] = va[p] ? *(const float4*)(Ap[p] + k0 + 32) : make_float4(0,0,0,0);
            #pragma unroll
            for (int p = 0; p < 2; p++)
                pb[p] = *(const float4*)(Bp[p] + k0 + 32);
        }
        #pragma unroll
        for (int ks = 0; ks < 4; ks++) {
            const int kb = ks*8;
            unsigned af[2][4], bf[4][2];
            #pragma unroll
            for (int i = 0; i < 2; i++) {
                af[i][0] = s.As[wm+i*16+g  ][kb+tg];
                af[i][1] = s.As[wm+i*16+8+g][kb+tg];
                af[i][2] = s.As[wm+i*16+g  ][kb+tg+4];
                af[i][3] = s.As[wm+i*16+8+g][kb+tg+4];
            }
            #pragma unroll
            for (int j = 0; j < 4; j++) {
                bf[j][0] = s.Bs[wn+j*8+g][kb+tg];
                bf[j][1] = s.Bs[wn+j*8+g][kb+tg+4];
            }
            #pragma unroll
            for (int i = 0; i < 2; i++)
                #pragma unroll
                for (int j = 0; j < 4; j++)
                    mma8(acc[i][j], af[i], bf[j]);
        }
        __syncthreads();
        if (nxt) {
            #pragma unroll
            for (int p = 0; p < 4; p++) {
                s.As[p*32+ar][ac+0]=f2tf32(pa[p].x); s.As[p*32+ar][ac+1]=f2tf32(pa[p].y);
                s.As[p*32+ar][ac+2]=f2tf32(pa[p].z); s.As[p*32+ar][ac+3]=f2tf32(pa[p].w);
            }
            #pragma unroll
            for (int p = 0; p < 2; p++) {
                s.Bs[p*32+ar][ac+0]=f2tf32(pb[p].x); s.Bs[p*32+ar][ac+1]=f2tf32(pb[p].y);
                s.Bs[p*32+ar][ac+2]=f2tf32(pb[p].z); s.Bs[p*32+ar][ac+3]=f2tf32(pb[p].w);
            }
            __syncthreads();
        }
    }

    #pragma unroll
    for (int i = 0; i < 2; i++) {
        #pragma unroll
        for (int j = 0; j < 4; j++) {
            int r0 = row0 + wm + i*16 + g;
            int cc = col0 + wn + j*8 + tg*2;
            if (r0 < M) {
                size_t x = (size_t)r0*N + cc;
                float v0 = acc[i][j][0], v1 = acc[i][j][1];
                if (R) { v0 += R[x]; v1 += R[x+1]; }
                C[x] = v0; C[x+1] = v1;
            }
            int r1 = r0 + 8;
            if (r1 < M) {
                size_t x = (size_t)r1*N + cc;
                float v2 = acc[i][j][2], v3 = acc[i][j][3];
                if (R) { v2 += R[x]; v3 += R[x+1]; }
                C[x] = v2; C[x+1] = v3;
            }
        }
    }
}

__global__ __launch_bounds__(256) void gemm_tf32_nt(
        const float* __restrict__ A, const float* __restrict__ B,
        const float* __restrict__ R, float* __restrict__ C, int M, int N, int K) {
    __shared__ SmemNT s;
    gemm_nt_body(s, A, B, R, C, M, N, K, blockIdx.y * 128, blockIdx.x * 64);
}

// =============== shared expert up + SiLU gate (dual-B tf32 NT) ============
// gt[T, DSH] = silu(x@B[0:DSH]^T) * (x@B[DSH:2DSH]^T). BM=128 BN=64 BK=32.
__global__ __launch_bounds__(256) void shared_up_gate_tf32(
        const float* __restrict__ A, const float* __restrict__ B,
        float* __restrict__ gt) {
    __shared__ unsigned As[128][36];
    __shared__ unsigned B1s[64][36];
    __shared__ unsigned B2s[64][36];
    const int row0 = blockIdx.y * 128, col0 = blockIdx.x * 64;
    const int tid = threadIdx.x;
    const int lane = tid & 31, w = tid >> 5;
    const int g = lane >> 2, tg = lane & 3;
    const int wm = (w & 3) * 32, wn = (w >> 2) * 32;
    const int ar = tid >> 3, ac = (tid & 7) * 4;

    const float* Ap[4];
    #pragma unroll
    for (int p = 0; p < 4; p++)
        Ap[p] = A + (size_t)(row0 + p*32 + ar) * DD + ac;
    const float* B1p[2]; const float* B2p[2];
    #pragma unroll
    for (int p = 0; p < 2; p++) {
        B1p[p] = B + (size_t)(col0 + p*32 + ar) * DD + ac;
        B2p[p] = B + (size_t)(DSH + col0 + p*32 + ar) * DD + ac;
    }

    #pragma unroll
    for (int p = 0; p < 4; p++) {
        float4 v = *(const float4*)(Ap[p]);
        As[p*32+ar][ac+0]=f2tf32(v.x); As[p*32+ar][ac+1]=f2tf32(v.y);
        As[p*32+ar][ac+2]=f2tf32(v.z); As[p*32+ar][ac+3]=f2tf32(v.w);
    }
    #pragma unroll
    for (int p = 0; p < 2; p++) {
        float4 v1 = *(const float4*)(B1p[p]);
        float4 v2 = *(const float4*)(B2p[p]);
        B1s[p*32+ar][ac+0]=f2tf32(v1.x); B1s[p*32+ar][ac+1]=f2tf32(v1.y);
        B1s[p*32+ar][ac+2]=f2tf32(v1.z); B1s[p*32+ar][ac+3]=f2tf32(v1.w);
        B2s[p*32+ar][ac+0]=f2tf32(v2.x); B2s[p*32+ar][ac+1]=f2tf32(v2.y);
        B2s[p*32+ar][ac+2]=f2tf32(v2.z); B2s[p*32+ar][ac+3]=f2tf32(v2.w);
    }
    __syncthreads();

    float acc1[2][4][4] = {}, acc2[2][4][4] = {};
    float4 pa[4], pb1[2], pb2[2];
    for (int k0 = 0; k0 < DD; k0 += 32) {
        bool nxt = (k0 + 32) < DD;
        if (nxt) {
            #pragma unroll
            for (int p = 0; p < 4; p++) pa[p] = *(const float4*)(Ap[p] + k0 + 32);
            #pragma unroll
            for (int p = 0; p < 2; p++) {
                pb1[p] = *(const float4*)(B1p[p] + k0 + 32);
                pb2[p] = *(const float4*)(B2p[p] + k0 + 32);
            }
        }
        #pragma unroll
        for (int ks = 0; ks < 4; ks++) {
            const int kb = ks*8;
            unsigned af[2][4], bf1[4][2], bf2[4][2];
            #pragma unroll
            for (int i = 0; i < 2; i++) {
                af[i][0] = As[wm+i*16+g  ][kb+tg];
                af[i][1] = As[wm+i*16+8+g][kb+tg];
                af[i][2] = As[wm+i*16+g  ][kb+tg+4];
                af[i][3] = As[wm+i*16+8+g][kb+tg+4];
            }
            #pragma unroll
            for (int j = 0; j < 4; j++) {
                bf1[j][0] = B1s[wn+j*8+g][kb+tg];
                bf1[j][1] = B1s[wn+j*8+g][kb+tg+4];
                bf2[j][0] = B2s[wn+j*8+g][kb+tg];
                bf2[j][1] = B2s[wn+j*8+g][kb+tg+4];
            }
            #pragma unroll
            for (int i = 0; i < 2; i++)
                #pragma unroll
                for (int j = 0; j < 4; j++) {
                    mma8(acc1[i][j], af[i], bf1[j]);
                    mma8(acc2[i][j], af[i], bf2[j]);
                }
        }
        __syncthreads();
        if (nxt) {
            #pragma unroll
            for (int p = 0; p < 4; p++) {
                As[p*32+ar][ac+0]=f2tf32(pa[p].x); As[p*32+ar][ac+1]=f2tf32(pa[p].y);
                As[p*32+ar][ac+2]=f2tf32(pa[p].z); As[p*32+ar][ac+3]=f2tf32(pa[p].w);
            }
            #pragma unroll
            for (int p = 0; p < 2; p++) {
                B1s[p*32+ar][ac+0]=f2tf32(pb1[p].x); B1s[p*32+ar][ac+1]=f2tf32(pb1[p].y);
                B1s[p*32+ar][ac+2]=f2tf32(pb1[p].z); B1s[p*32+ar][ac+3]=f2tf32(pb1[p].w);
                B2s[p*32+ar][ac+0]=f2tf32(pb2[p].x); B2s[p*32+ar][ac+1]=f2tf32(pb2[p].y);
                B2s[p*32+ar][ac+2]=f2tf32(pb2[p].z); B2s[p*32+ar][ac+3]=f2tf32(pb2[p].w);
            }
            __syncthreads();
        }
    }

    #pragma unroll
    for (int i = 0; i < 2; i++) {
        #pragma unroll
        for (int j = 0; j < 4; j++) {
            int r0 = row0 + wm + i*16 + g;
            int cc = col0 + wn + j*8 + tg*2;
            #pragma unroll
            for (int half = 0; half < 2; half++) {
                int r = r0 + half*8;
                float h1a = acc1[i][j][half*2+0], h2a = acc2[i][j][half*2+0];
                float h1b = acc1[i][j][half*2+1], h2b = acc2[i][j][half*2+1];
                float sa = 1.f / (1.f + __expf(-h1a));
                float sb = 1.f / (1.f + __expf(-h1b));
                size_t x = (size_t)r * DSH + cc;
                gt[x]   = h1a * sa * h2a;
                gt[x+1] = h1b * sb * h2b;
            }
        }
    }
}

// ---------------- RoPE (in-place on q,k within qkv buffer) ----------------
__global__ void rope_kernel(float* __restrict__ qkv) {
    int idx = blockIdx.x * blockDim.x + threadIdx.x;
    const int total = 2 * TT * HH * 32;
    if (idx >= total) return;
    int which = idx / (TT * HH * 32);
    int rem   = idx % (TT * HH * 32);
    int t = rem / (HH * 32);
    int r2 = rem % (HH * 32);
    int h = r2 >> 5, i = r2 & 31;
    size_t base = (size_t)t * QKV3 + (size_t)which * DD + h * HDIM;
    float invf = (float)exp(-9.210340371976184 * ((double)i / 32.0));
    float fr = (float)t * invf;
    float c = (float)cos((double)fr);
    float s = (float)sin((double)fr);
    float x1 = qkv[base + i];
    float x2 = qkv[base + 32 + i];
    qkv[base + i]      =  x1 * c + x2 * s;
    qkv[base + 32 + i] = -x1 * s + x2 * c;
}

// =============== flash attention, tf32 tensor cores ======================
// 64q x 64k tiles, 256 threads = 8 warps in 4(M) x 2(N) fragment grid.
// Qs/Ks/Vs tf32 in smem (stride 68, conflict-free fragment loads),
// smem round-trip softmax on Ps (fp32).
#define ASTR 68
__global__ __launch_bounds__(256) void attn_kernel(const float* __restrict__ qkv,
                                                   float* __restrict__ o) {
    extern __shared__ float sm[];
    unsigned* Qs = (unsigned*)sm;            // [64][ASTR] q-major [q][d]
    unsigned* Ks = Qs + 64*ASTR;             // [64][ASTR] [kcol][d]
    unsigned* Vs = Ks + 64*ASTR;             // [64][ASTR] [k][d]
    float*    Ps = sm + 3*64*ASTR;           // [64][ASTR] [q][k]
    float* mrow = Ps + 64*ASTR;
    float* lrow = mrow + 64;
    float* arow = lrow + 64;

    const int qb = gridDim.x - 1 - blockIdx.x;   // heavy blocks first
    const int h = blockIdx.y;
    const int tid = threadIdx.x;
    const int lane = tid & 31, w = tid >> 5;
    const int g = lane >> 2, tg = lane & 3;
    const int wm = (w & 3) * 16, wn = (w >> 2) * 32;

    { // load Q tile as tf32
        int qi = tid >> 2, d0 = (tid & 3) << 2;
        #pragma unroll
        for (int dp = 0; dp < 64; dp += 16) {
            float4 v = *(const float4*)(qkv + (size_t)(qb*64+qi)*QKV3 + h*HDIM + dp + d0);
            Qs[qi*ASTR + dp+d0+0]=f2tf32(v.x); Qs[qi*ASTR + dp+d0+1]=f2tf32(v.y);
            Qs[qi*ASTR + dp+d0+2]=f2tf32(v.z); Qs[qi*ASTR + dp+d0+3]=f2tf32(v.w);
        }
    }
    if (tid < 64) { mrow[tid] = -INFINITY; lrow[tid] = 0.f; }
    float acco[4][4] = {};

    for (int kb = 0; kb <= qb; kb++) {
        __syncthreads();
        { // load K, V tiles as tf32
            int ki = tid >> 2, d0 = (tid & 3) << 2;
            #pragma unroll
            for (int dp = 0; dp < 64; dp += 16) {
                float4 kv = *(const float4*)(qkv + (size_t)(kb*64+ki)*QKV3 + DD + h*HDIM + dp + d0);
                Ks[ki*ASTR + dp+d0+0]=f2tf32(kv.x); Ks[ki*ASTR + dp+d0+1]=f2tf32(kv.y);
                Ks[ki*ASTR + dp+d0+2]=f2tf32(kv.z); Ks[ki*ASTR + dp+d0+3]=f2tf32(kv.w);
                float4 vv = *(const float4*)(qkv + (size_t)(kb*64+ki)*QKV3 + 2*DD + h*HDIM + dp + d0);
                Vs[ki*ASTR + dp+d0+0]=f2tf32(vv.x); Vs[ki*ASTR + dp+d0+1]=f2tf32(vv.y);
                Vs[ki*ASTR + dp+d0+2]=f2tf32(vv.z); Vs[ki*ASTR + dp+d0+3]=f2tf32(vv.w);
            }
        }
        __syncthreads();

        // S = Q @ K^T  (warp tile: rows wm..wm+15, cols wn..wn+31)
        float sf[4][4] = {};
        #pragma unroll
        for (int kk = 0; kk < 8; kk++) {
            unsigned a[4];
            a[0] = Qs[(wm+g  )*ASTR + kk*8+tg];
            a[1] = Qs[(wm+8+g)*ASTR + kk*8+tg];
            a[2] = Qs[(wm+g  )*ASTR + kk*8+tg+4];
            a[3] = Qs[(wm+8+g)*ASTR + kk*8+tg+4];
            #pragma unroll
            for (int j = 0; j < 4; j++) {
                unsigned b[2] = { Ks[(wn+j*8+g)*ASTR + kk*8+tg],
                                  Ks[(wn+j*8+g)*ASTR + kk*8+tg+4] };
                mma8(sf[j], a, b);
            }
        }
        // scale + causal mask + store to Ps[q][k]
        {
            int q0 = qb*64 + wm + g, q1 = q0 + 8;
            #pragma unroll
            for (int j = 0; j < 4; j++) {
                int c0 = wn + j*8 + tg*2;
                int kg = kb*64 + c0;
                float v0 = sf[j][0]*0.125f, v1 = sf[j][1]*0.125f;
                float v2 = sf[j][2]*0.125f, v3 = sf[j][3]*0.125f;
                if (kg   > q0) v0 = -1e30f;
                if (kg+1 > q0) v1 = -1e30f;
                if (kg   > q1) v2 = -1e30f;
                if (kg+1 > q1) v3 = -1e30f;
                Ps[(wm+g  )*ASTR + c0] = v0; Ps[(wm+g  )*ASTR + c0+1] = v1;
                Ps[(wm+8+g)*ASTR + c0] = v2; Ps[(wm+8+g)*ASTR + c0+1] = v3;
            }
        }
        __syncthreads();
        { // online softmax, 4 threads per row
            int r = tid >> 2, cb = (tid & 3) * 16;
            float vmax = -INFINITY;
            #pragma unroll
            for (int c = 0; c < 16; c++) vmax = fmaxf(vmax, Ps[r*ASTR + cb + c]);
            vmax = fmaxf(vmax, __shfl_xor_sync(0xffffffffu, vmax, 1));
            vmax = fmaxf(vmax, __shfl_xor_sync(0xffffffffu, vmax, 2));
            float mold = mrow[r];
            float mnew = fmaxf(mold, vmax);
            float psum = 0.f;
            #pragma unroll
            for (int c = 0; c < 16; c++) {
                float p = __expf(Ps[r*ASTR + cb + c] - mnew);
                Ps[r*ASTR + cb + c] = p;
                psum += p;
            }
            psum += __shfl_xor_sync(0xffffffffu, psum, 1);
            psum += __shfl_xor_sync(0xffffffffu, psum, 2);
            float alpha = __expf(mold - mnew);
            if ((tid & 3) == 0) { mrow[r] = mnew; lrow[r] = lrow[r]*alpha + psum; arow[r] = alpha; }
        }
        __syncthreads();
        // rescale output accumulators
        {
            float a0 = arow[wm+g], a1 = arow[wm+8+g];
            #pragma unroll
            for (int j = 0; j < 4; j++) {
                acco[j][0] *= a0; acco[j][1] *= a0;
                acco[j][2] *= a1; acco[j][3] *= a1;
            }
        }
        // O += P @ V  (warp tile: rows wm..wm+15, d cols wn..wn+31)
        #pragma unroll
        for (int kk = 0; kk < 8; kk++) {
            unsigned a[4];
            a[0] = f2tf32(Ps[(wm+g  )*ASTR + kk*8+tg]);
            a[1] = f2tf32(Ps[(wm+8+g)*ASTR + kk*8+tg]);
            a[2] = f2tf32(Ps[(wm+g  )*ASTR + kk*8+tg+4]);
            a[3] = f2tf32(Ps[(wm+8+g)*ASTR + kk*8+tg+4]);
            #pragma unroll
            for (int j = 0; j < 4; j++) {
                unsigned b[2] = { Vs[(kk*8+tg  )*ASTR + wn+j*8+g],
                                  Vs[(kk*8+tg+4)*ASTR + wn+j*8+g] };
                mma8(acco[j], a, b);
            }
        }
    }

    // epilogue: divide by l and store
    {
        float l0 = 1.f / lrow[wm+g], l1 = 1.f / lrow[wm+8+g];
        int q0 = qb*64 + wm + g, q1 = q0 + 8;
        #pragma unroll
        for (int j = 0; j < 4; j++) {
            int col = h*HDIM + wn + j*8 + tg*2;
            o[(size_t)q0*DD + col]   = acco[j][0] * l0;
            o[(size_t)q0*DD + col+1] = acco[j][1] * l0;
            o[(size_t)q1*DD + col]   = acco[j][2] * l1;
            o[(size_t)q1*DD + col+1] = acco[j][3] * l1;
        }
    }
}

// ---------------- router ----------------
__global__ void router_kernel(const float* __restrict__ xffn, const float* __restrict__ mk,
                              const float* __restrict__ bias, const int* __restrict__ indices,
                              const float* __restrict__ values, float* __restrict__ scores) {
    int t = blockIdx.x;
    __shared__ float red[128 * NEXP];
    float partial[NEXP];
    #pragma unroll
    for (int e = 0; e < NEXP; e++) partial[e] = 0.f;
    for (int d = threadIdx.x; d < DD; d += 128) {
        float xv = xffn[(size_t)t*DD + d];
        const float* mrow = mk + (size_t)d * NEXP;
        #pragma unroll
        for (int e = 0; e < NEXP; e++) partial[e] += xv * mrow[e];
    }
    #pragma unroll
    for (int e = 0; e < NEXP; e++) red[threadIdx.x*NEXP + e] = partial[e];
    __syncthreads();
    for (int s = 64; s >= 1; s >>= 1) {
        if (threadIdx.x < s)
            #pragma unroll
            for (int e = 0; e < NEXP; e++)
                red[threadIdx.x*NEXP + e] += red[(threadIdx.x+s)*NEXP + e];
        __syncthreads();
    }
    if (threadIdx.x == 0) {
        int i0 = indices[t*2+0], i1 = indices[t*2+1];
        float v0 = values[t*2+0] + red[i0] + bias[i0];
        float v1 = values[t*2+1] + red[i1] + bias[i1];
        float m = fmaxf(v0, v1);
        float e0 = __expf(v0 - m), e1 = __expf(v1 - m);
        float inv = 1.f / (e0 + e1);
        scores[t*2+0] = e0 * inv;
        scores[t*2+1] = e1 * inv;
    }
}

// ---------------- routing build ----------------
__global__ void route_init(int* counts) { if (threadIdx.x < NEXP) counts[threadIdx.x] = 0; }
__global__ void route_count(const int* __restrict__ indices, int* counts) {
    int i = blockIdx.x * blockDim.x + threadIdx.x;
    if (i < TT*TOPK) atomicAdd(&counts[indices[i]], 1);
}
__global__ void route_scan(const int* __restrict__ counts, int* offsets, int* cursor) {
    if (threadIdx.x == 0) {
        int off = 0;
        for (int e = 0; e < NEXP; e++) { offsets[e] = off; cursor[e] = off; off += counts[e]; }
        offsets[NEXP] = off;
    }
}
__global__ void route_scatter(const int* __restrict__ indices, int* cursor,
                              int* __restrict__ perm, int* __restrict__ slotpos) {
    int i = blockIdx.x * blockDim.x + threadIdx.x;
    if (i < TT*TOPK) {
        int e = indices[i];
        int p = atomicAdd(&cursor[e], 1);
        perm[p] = i >> 1;
        slotpos[i] = p;
    }
}

// =============== expert up (tf32): g = silu(x@W1) * (x@W2), gathered A ====
__global__ __launch_bounds__(256) void expert_up_tf32(
        const float* __restrict__ xffn, const float* __restrict__ experts,
        const int* __restrict__ counts, const int* __restrict__ offsets,
        const int* __restrict__ perm, float* __restrict__ g_out) {
    const int e = blockIdx.z;
    const int M = counts[e];
    const int row0 = blockIdx.y * 64;
    if (row0 >= M) return;
    const int off = offsets[e];
    const float* B1 = experts + (size_t)e * DD * EDIM;
    const float* B2 = experts + ((size_t)NEXP + e) * DD * EDIM;
    const int col0 = blockIdx.x * 64;

    __shared__ unsigned As[64][36];
    __shared__ unsigned B1s[32][72];
    __shared__ unsigned B2s[32][72];

    const int tid = threadIdx.x;
    const int lane = tid & 31, w = tid >> 5;
    const int g = lane >> 2, tg = lane & 3;
    const int wm = (w & 1) * 32, wn = (w >> 1) * 16;
    const int ar = tid >> 3, ac = (tid & 7) * 4;
    const int bkr = tid >> 4, bnc = (tid & 15) * 4;

    const float* Ap[2]; bool va[2];
    #pragma unroll
    for (int p = 0; p < 2; p++) {
        int r = row0 + p*32 + ar;
        va[p] = r < M;
        int tok = va[p] ? perm[off + r] : 0;
        Ap[p] = xffn + (size_t)tok * DD + ac;
    }
    const float* B1p[2]; const float* B2p[2];
    #pragma unroll
    for (int p = 0; p < 2; p++) {
        B1p[p] = B1 + (size_t)(p*16 + bkr) * EDIM + col0 + bnc;
        B2p[p] = B2 + (size_t)(p*16 + bkr) * EDIM + col0 + bnc;
    }

    #pragma unroll
    for (int p = 0; p < 2; p++) {
        float4 v = va[p] ? *(const float4*)(Ap[p]) : make_float4(0,0,0,0);
        As[p*32+ar][ac+0]=f2tf32(v.x); As[p*32+ar][ac+1]=f2tf32(v.y);
        As[p*32+ar][ac+2]=f2tf32(v.z); As[p*32+ar][ac+3]=f2tf32(v.w);
    }
    #pragma unroll
    for (int p = 0; p < 2; p++) {
        float4 v1 = *(const float4*)(B1p[p]);
        float4 v2 = *(const float4*)(B2p[p]);
        B1s[p*16+bkr][bnc+0]=f2tf32(v1.x); B1s[p*16+bkr][bnc+1]=f2tf32(v1.y);
        B1s[p*16+bkr][bnc+2]=f2tf32(v1.z); B1s[p*16+bkr][bnc+3]=f2tf32(v1.w);
        B2s[p*16+bkr][bnc+0]=f2tf32(v2.x); B2s[p*16+bkr][bnc+1]=f2tf32(v2.y);
        B2s[p*16+bkr][bnc+2]=f2tf32(v2.z); B2s[p*16+bkr][bnc+3]=f2tf32(v2.w);
    }
    __syncthreads();

    float acc1[2][2][4] = {}, acc2[2][2][4] = {};
    float4 pa[2], pb1[2], pb2[2];
    for (int k0 = 0; k0 < DD; k0 += 32) {
        bool nxt = (k0 + 32) < DD;
        if (nxt) {
            #pragma unroll
            for (int p = 0; p < 2; p++)
                pa[p] = va[p] ? *(const float4*)(Ap[p] + k0 + 32) : make_float4(0,0,0,0);
            #pragma unroll
            for (int p = 0; p < 2; p++) {
                pb1[p] = *(const float4*)(B1p[p] + (size_t)(k0 + 32) * EDIM);
                pb2[p] = *(const float4*)(B2p[p] + (size_t)(k0 + 32) * EDIM);
            }
        }
        #pragma unroll
        for (int ks = 0; ks < 4; ks++) {
            const int kb = ks*8;
            unsigned af[2][4], bf1[2][2], bf2[2][2];
            #pragma unroll
            for (int i = 0; i < 2; i++) {
                af[i][0] = As[wm+i*16+g  ][kb+tg];
                af[i][1] = As[wm+i*16+8+g][kb+tg];
                af[i][2] = As[wm+i*16+g  ][kb+tg+4];
                af[i][3] = As[wm+i*16+8+g][kb+tg+4];
            }
            #pragma unroll
            for (int j = 0; j < 2; j++) {
                bf1[j][0] = B1s[kb+tg  ][wn+j*8+g];
                bf1[j][1] = B1s[kb+tg+4][wn+j*8+g];
                bf2[j][0] = B2s[kb+tg  ][wn+j*8+g];
                bf2[j][1] = B2s[kb+tg+4][wn+j*8+g];
            }
            #pragma unroll
            for (int i = 0; i < 2; i++)
                #pragma unroll
                for (int j = 0; j < 2; j++) {
                    mma8(acc1[i][j], af[i], bf1[j]);
                    mma8(acc2[i][j], af[i], bf2[j]);
                }
        }
        __syncthreads();
        if (nxt) {
            #pragma unroll
            for (int p = 0; p < 2; p++) {
                As[p*32+ar][ac+0]=f2tf32(pa[p].x); As[p*32+ar][ac+1]=f2tf32(pa[p].y);
                As[p*32+ar][ac+2]=f2tf32(pa[p].z); As[p*32+ar][ac+3]=f2tf32(pa[p].w);
            }
            #pragma unroll
            for (int p = 0; p < 2; p++) {
                B1s[p*16+bkr][bnc+0]=f2tf32(pb1[p].x); B1s[p*16+bkr][bnc+1]=f2tf32(pb1[p].y);
                B1s[p*16+bkr][bnc+2]=f2tf32(pb1[p].z); B1s[p*16+bkr][bnc+3]=f2tf32(pb1[p].w);
                B2s[p*16+bkr][bnc+0]=f2tf32(pb2[p].x); B2s[p*16+bkr][bnc+1]=f2tf32(pb2[p].y);
                B2s[p*16+bkr][bnc+2]=f2tf32(pb2[p].z); B2s[p*16+bkr][bnc+3]=f2tf32(pb2[p].w);
            }
            __syncthreads();
        }
    }

    #pragma unroll
    for (int i = 0; i < 2; i++) {
        #pragma unroll
        for (int j = 0; j < 2; j++) {
            int r0 = row0 + wm + i*16 + g;
            int cc = col0 + wn + j*8 + tg*2;
            #pragma unroll
            for (int half = 0; half < 2; half++) {
                int r = r0 + half*8;
                if (r < M) {
                    float h1a = acc1[i][j][half*2+0], h2a = acc2[i][j][half*2+0];
                    float h1b = acc1[i][j][half*2+1], h2b = acc2[i][j][half*2+1];
                    float sa = 1.f / (1.f + __expf(-h1a));
                    float sb = 1.f / (1.f + __expf(-h1b));
                    size_t x = (size_t)(off + r) * EDIM + cc;
                    g_out[x]   = h1a * sa * h2a;
                    g_out[x+1] = h1b * sb * h2b;
                }
            }
        }
    }
}

// =============== expert down (tf32 NT): yp = g @ W3^T, per-expert slabs ===
__global__ __launch_bounds__(256) void expert_down_tf32(
        const float* __restrict__ gbuf, const float* __restrict__ experts,
        const int* __restrict__ counts, const int* __restrict__ offsets,
        float* __restrict__ yp) {
    const int e = blockIdx.z;
    const int M = counts[e];
    const int row0 = blockIdx.y * 128;
    if (row0 >= M) return;
    const int off = offsets[e];
    __shared__ SmemNT s;
    gemm_nt_body(s,
                 gbuf + (size_t)off * EDIM,
                 experts + (2*(size_t)NEXP + e) * DD * EDIM,
                 nullptr,
                 yp + (size_t)off * DD,
                 M, DD, EDIM, row0, blockIdx.x * 64);
}

// ---------------- combine experts (scores * yp) * coeff -------------------
__global__ void combine_kernel(const float* __restrict__ yp, const float* __restrict__ scores,
                               const int* __restrict__ slotpos, const float* __restrict__ coeff,
                               float* __restrict__ ycomb) {
    int t = blockIdx.x;
    float s0 = scores[t*2+0], s1 = scores[t*2+1];
    int p0 = slotpos[t*2+0], p1 = slotpos[t*2+1];
    const float* r0 = yp + (size_t)p0 * DD;
    const float* r1 = yp + (size_t)p1 * DD;
    #pragma unroll
    for (int i = 0; i < 4; i++) {
        int d = threadIdx.x + i*256;
        ycomb[(size_t)t*DD + d] = (s0*r0[d] + s1*r1[d]) * coeff[d];
    }
}

// ---------------- final: out = ycomb + rmsnorm(ysh)*w + x_ffn_input ------
__global__ void final_kernel(const float* __restrict__ ycomb, const float* __restrict__ ysh,
                             const float* __restrict__ shw, const float* __restrict__ xfi,
                             float* __restrict__ out) {
    int t = blockIdx.x;
    const float* yr = ysh + (size_t)t * DD;
    float v[4]; float s = 0.f;
    #pragma unroll
    for (int i = 0; i < 4; i++) { v[i] = yr[threadIdx.x + i*256]; s += v[i]*v[i]; }
    __shared__ float red[8];
    #pragma unroll
    for (int off = 16; off > 0; off >>= 1) s += __shfl_xor_sync(0xffffffffu, s, off);
    if ((threadIdx.x & 31) == 0) red[threadIdx.x >> 5] = s;
    __syncthreads();
    if (threadIdx.x == 0) {
        float tot = 0.f;
        #pragma unroll
        for (int i = 0; i < 8; i++) tot += red[i];
        red[0] = tot;
    }
    __syncthreads();
    float sc = rsqrtf(red[0] / (float)DD + 1e-5f);
    #pragma unroll
    for (int i = 0; i < 4; i++) {
        int d = threadIdx.x + i*256;
        size_t idx = (size_t)t*DD + d;
        out[idx] = ycomb[idx] + v[i]*sc*shw[d] + xfi[idx];
    }
}

// ---------------- launch ----------------
extern "C" void kernel_launch(void* const* d_in, const int* in_sizes, int n_in,
                              void* d_out, int out_size) {
    const float* x_input     = (const float*)d_in[0];
    const int*   indices     = (const int*)  d_in[1];
    const float* values      = (const float*)d_in[2];
    const float* attn_w      = (const float*)d_in[3];
    const float* attn_o_w    = (const float*)d_in[4];
    const float* attn_norm_w = (const float*)d_in[5];
    const float* ffn_norm_w  = (const float*)d_in[6];
    const float* ffn_experts = (const float*)d_in[7];
    const float* main_keys   = (const float*)d_in[8];
    const float* main_bias   = (const float*)d_in[9];
    const float* out_coeff   = (const float*)d_in[10];
    const float* ffn_up_w    = (const float*)d_in[11];
    const float* ffn_down_w  = (const float*)d_in[12];
    const float* shared_nw   = (const float*)d_in[13];
    float* out = (float*)d_out;

    float* bufF = nullptr; int* bufI = nullptr;
    cudaGetSymbolAddress((void**)&bufF, g_bufF);
    cudaGetSymbolAddress((void**)&bufI, g_bufI);

    float* xn   = bufF + OFF_XN;
    float* qkv  = bufF + OFF_QKV;
    float* ao   = bufF + OFF_AO;
    float* xfi  = bufF + OFF_XFI;
    float* xfn  = bufF + OFF_XFN;
    float* sc   = bufF + OFF_SC;
    float* gbuf = bufF + OFF_G;
    float* yp   = bufF + OFF_YP;
    float* yc   = bufF + OFF_YC;
    float* gt   = bufF + OFF_GT;
    float* ys   = bufF + OFF_YS;

    int* cnt  = bufI + IOFF_CNT;
    int* offs = bufI + IOFF_OFFS;
    int* cur  = bufI + IOFF_CUR;
    int* perm = bufI + IOFF_PERM;
    int* slot = bufI + IOFF_SLOT;

    const int ATTN_SMEM = (4*64*ASTR + 3*64) * sizeof(float);
    cudaFuncSetAttribute(attn_kernel, cudaFuncAttributeMaxDynamicSharedMemorySize, ATTN_SMEM);

    // 1. attention pre-norm
    rmsnorm_kernel<<<TT, 256>>>(x_input, attn_norm_w, xn);
    // 2. QKV (tf32 tensor)
    gemm_tf32_nt<<<dim3(QKV3/64, TT/128), 256>>>(xn, attn_w, nullptr, qkv, TT, QKV3, DD);
    // 3. RoPE on q,k
    rope_kernel<<<(2*TT*HH*32 + 255)/256, 256>>>(qkv);
    // 4. attention (tf32 tensor)
    attn_kernel<<<dim3(TT/64, HH), 256, ATTN_SMEM>>>(qkv, ao);
    // 5. O proj + residual (tf32)
    gemm_tf32_nt<<<dim3(DD/64, TT/128), 256>>>(ao, attn_o_w, x_input, xfi, TT, DD, DD);
    // 6. ffn pre-norm
    rmsnorm_kernel<<<TT, 256>>>(xfi, ffn_norm_w, xfn);
    // 7. router scores
    router_kernel<<<TT, 128>>>(xfn, main_keys, main_bias, indices, values, sc);
    // 8. routing permutation
    route_init<<<1, 32>>>(cnt);
    route_count<<<(TT*TOPK + 255)/256, 256>>>(indices, cnt);
    route_scan<<<1, 32>>>(cnt, offs, cur);
    route_scatter<<<(TT*TOPK + 255)/256, 256>>>(indices, cur, perm, slot);
    // 9. expert up (tf32 dual GEMM + SiLU)
    expert_up_tf32<<<dim3(EDIM/64, (TT*TOPK)/64, NEXP), 256>>>(xfn, ffn_experts, cnt, offs, perm, gbuf);
    // 10. expert down (tf32)
    expert_down_tf32<<<dim3(DD/64, (TT*TOPK)/128, NEXP), 256>>>(gbuf, ffn_experts, cnt, offs, yp);
    // 11. combine
    combine_kernel<<<TT, 256>>>(yp, sc, slot, out_coeff, yc);
    // 12. shared expert up + gate (fused dual-B tf32)
    shared_up_gate_tf32<<<dim3(DSH/64, TT/128), 256>>>(xfn, ffn_up_w, gt);
    // 13. shared expert down (tf32)
    gemm_tf32_nt<<<dim3(DD/64, TT/128), 256>>>(gt, ffn_down_w, nullptr, ys, TT, DD, DSH);
    // 14. final combine
    final_kernel<<<TT, 256>>>(yc, ys, shared_nw, xfi, out);
}

// round 10
// speedup vs baseline: 2.6690x; 1.0109x over previous
#include <cuda_runtime.h>
#include <cuda_bf16.h>
#include <math.h>

#define TT    2048   // tokens (B*S)
#define DD    1024   // model dim
#define HH    16     // heads
#define HDIM  64     // head dim
#define NEXP  16     // experts
#define TOPK  2
#define EDIM  512    // expert dim
#define DSH   2048   // shared expert dim
#define QKV3  3072

// ---------------- scratch (device globals; no allocations) ----------------
constexpr size_t SZ_XN  = (size_t)TT * DD;
constexpr size_t OFF_XN  = 0;
constexpr size_t OFF_QKV = OFF_XN  + SZ_XN;
constexpr size_t OFF_AO  = OFF_QKV + (size_t)TT * QKV3;
constexpr size_t OFF_XFI = OFF_AO  + SZ_XN;
constexpr size_t OFF_XFN = OFF_XFI + SZ_XN;
constexpr size_t OFF_SC  = OFF_XFN + SZ_XN;
constexpr size_t OFF_G   = OFF_SC  + (size_t)TT * TOPK;
constexpr size_t OFF_YP  = OFF_G   + (size_t)TT * TOPK * EDIM;
constexpr size_t OFF_YC  = OFF_YP  + (size_t)TT * TOPK * DD;
constexpr size_t OFF_GT  = OFF_YC  + SZ_XN;
constexpr size_t OFF_YS  = OFF_GT  + (size_t)TT * DSH;
constexpr size_t TOTF    = OFF_YS  + SZ_XN;

__device__ float g_bufF[TOTF];

constexpr int IOFF_CNT  = 0;
constexpr int IOFF_OFFS = 16;
constexpr int IOFF_CUR  = 33;
constexpr int IOFF_PERM = 64;
constexpr int IOFF_SLOT = 64 + TT*TOPK;
constexpr int TOTI      = 64 + 2*TT*TOPK;
__device__ int g_bufI[TOTI];

// ---------------- tf32 mma helpers ----------------
__device__ __forceinline__ unsigned f2tf32(float x) {
    unsigned u; asm("cvt.rna.tf32.f32 %0, %1;" : "=r"(u) : "f"(x)); return u;
}
__device__ __forceinline__ void mma8(float* c, const unsigned* a, const unsigned* b) {
    asm volatile("mma.sync.aligned.m16n8k8.row.col.f32.tf32.tf32.f32 "
        "{%0,%1,%2,%3},{%4,%5,%6,%7},{%8,%9},{%0,%1,%2,%3};"
        : "+f"(c[0]), "+f"(c[1]), "+f"(c[2]), "+f"(c[3])
        : "r"(a[0]), "r"(a[1]), "r"(a[2]), "r"(a[3]), "r"(b[0]), "r"(b[1]));
}

// ---------------- rmsnorm ----------------
__global__ void rmsnorm_kernel(const float* __restrict__ x, const float* __restrict__ w,
                               float* __restrict__ o) {
    int t = blockIdx.x;
    const float* xr = x + (size_t)t * DD;
    float v[4]; float s = 0.f;
    #pragma unroll
    for (int i = 0; i < 4; i++) { v[i] = xr[threadIdx.x + i*256]; s += v[i]*v[i]; }
    __shared__ float red[8];
    #pragma unroll
    for (int off = 16; off > 0; off >>= 1) s += __shfl_xor_sync(0xffffffffu, s, off);
    if ((threadIdx.x & 31) == 0) red[threadIdx.x >> 5] = s;
    __syncthreads();
    if (threadIdx.x == 0) {
        float tot = 0.f;
        #pragma unroll
        for (int i = 0; i < 8; i++) tot += red[i];
        red[0] = tot;
    }
    __syncthreads();
    float sc = rsqrtf(red[0] / (float)DD + 1e-5f);
    #pragma unroll
    for (int i = 0; i < 4; i++) {
        int d = threadIdx.x + i*256;
        o[(size_t)t*DD + d] = v[i] * sc * w[d];
    }
}

// =============== tf32 NT GEMM: C[M,N] = A[M,K] @ B[N,K]^T (+R) ===========
// BM=128 BN=128 BK=32, 256 threads (8 warps: 2 along M x 4 along N,
// each warp computes a 64x32 tile -> 1.5 LDS per mma).
struct SmemNT {
    unsigned As[128][36];
    unsigned Bs[128][36];
};

__device__ __forceinline__ void gemm_nt_body(
        SmemNT& s, const float* __restrict__ A, const float* __restrict__ B,
        const float* __restrict__ R, float* __restrict__ C,
        int M, int N, int K, int row0, int col0) {
    const int tid = threadIdx.x;
    const int lane = tid & 31, w = tid >> 5;
    const int g = lane >> 2, tg = lane & 3;
    const int wm = (w & 1) * 64, wn = (w >> 1) * 32;
    const int ar = tid >> 3, ac = (tid & 7) * 4;

    const float* Ap[4]; bool va[4];
    #pragma unroll
    for (int p = 0; p < 4; p++) {
        int r = row0 + p*32 + ar;
        va[p] = r < M;
        Ap[p] = A + (size_t)(va[p] ? r : 0) * K + ac;
    }
    const float* Bp[4];
    #pragma unroll
    for (int p = 0; p < 4; p++)
        Bp[p] = B + (size_t)(col0 + p*32 + ar) * K + ac;

    #pragma unroll
    for (int p = 0; p < 4; p++) {
        float4 v = va[p] ? *(const float4*)(Ap[p]) : make_float4(0,0,0,0);
        s.As[p*32+ar][ac+0]=f2tf32(v.x); s.As[p*32+ar][ac+1]=f2tf32(v.y);
        s.As[p*32+ar][ac+2]=f2tf32(v.z); s.As[p*32+ar][ac+3]=f2tf32(v.w);
        float4 b = *(const float4*)(Bp[p]);
        s.Bs[p*32+ar][ac+0]=f2tf32(b.x); s.Bs[p*32+ar][ac+1]=f2tf32(b.y);
        s.Bs[p*32+ar][ac+2]=f2tf32(b.z); s.Bs[p*32+ar][ac+3]=f2tf32(b.w);
    }
    __syncthreads();

    float acc[4][4][4] = {};
    float4 pa[4], pb[4];
    for (int k0 = 0; k0 < K; k0 += 32) {
        bool nxt = (k0 + 32) < K;
        if (nxt) {
            #pragma unroll
            for (int p = 0; p < 4; p++) {
                pa[p] = va[p] ? *(const float4*)(Ap[p] + k0 + 32) : make_float4(0,0,0,0);
                pb[p] = *(const float4*)(Bp[p] + k0 + 32);
            }
        }
        #pragma unroll
        for (int ks = 0; ks < 4; ks++) {
            const int kb = ks*8;
            unsigned af[4][4], bf[4][2];
            #pragma unroll
            for (int i = 0; i < 4; i++) {
                af[i][0] = s.As[wm+i*16+g  ][kb+tg];
                af[i][1] = s.As[wm+i*16+8+g][kb+tg];
                af[i][2] = s.As[wm+i*16+g  ][kb+tg+4];
                af[i][3] = s.As[wm+i*16+8+g][kb+tg+4];
            }
            #pragma unroll
            for (int j = 0; j < 4; j++) {
                bf[j][0] = s.Bs[wn+j*8+g][kb+tg];
                bf[j][1] = s.Bs[wn+j*8+g][kb+tg+4];
            }
            #pragma unroll
            for (int i = 0; i < 4; i++)
                #pragma unroll
                for (int j = 0; j < 4; j++)
                    mma8(acc[i][j], af[i], bf[j]);
        }
        __syncthreads();
        if (nxt) {
            #pragma unroll
            for (int p = 0; p < 4; p++) {
                s.As[p*32+ar][ac+0]=f2tf32(pa[p].x); s.As[p*32+ar][ac+1]=f2tf32(pa[p].y);
                s.As[p*32+ar][ac+2]=f2tf32(pa[p].z); s.As[p*32+ar][ac+3]=f2tf32(pa[p].w);
                s.Bs[p*32+ar][ac+0]=f2tf32(pb[p].x); s.Bs[p*32+ar][ac+1]=f2tf32(pb[p].y);
                s.Bs[p*32+ar][ac+2]=f2tf32(pb[p].z); s.Bs[p*32+ar][ac+3]=f2tf32(pb[p].w);
            }
            __syncthreads();
        }
    }

    #pragma unroll
    for (int i = 0; i < 4; i++) {
        #pragma unroll
        for (int j = 0; j < 4; j++) {
            int r0 = row0 + wm + i*16 + g;
            int cc = col0 + wn + j*8 + tg*2;
            if (r0 < M) {
                size_t x = (size_t)r0*N + cc;
                float v0 = acc[i][j][0], v1 = acc[i][j][1];
                if (R) { v0 += R[x]; v1 += R[x+1]; }
                C[x] = v0; C[x+1] = v1;
            }
            int r1 = r0 + 8;
            if (r1 < M) {
                size_t x = (size_t)r1*N + cc;
                float v2 = acc[i][j][2], v3 = acc[i][j][3];
                if (R) { v2 += R[x]; v3 += R[x+1]; }
                C[x] = v2; C[x+1] = v3;
            }
        }
    }
}

__global__ __launch_bounds__(256) void gemm_tf32_nt(
        const float* __restrict__ A, const float* __restrict__ B,
        const float* __restrict__ R, float* __restrict__ C, int M, int N, int K) {
    __shared__ SmemNT s;
    gemm_nt_body(s, A, B, R, C, M, N, K, blockIdx.y * 128, blockIdx.x * 128);
}

// =============== shared expert up + SiLU gate (dual-B tf32 NT) ============
// gt[T, DSH] = silu(x@B[0:DSH]^T) * (x@B[DSH:2DSH]^T). BM=128 BN=64 BK=32.
__global__ __launch_bounds__(256) void shared_up_gate_tf32(
        const float* __restrict__ A, const float* __restrict__ B,
        float* __restrict__ gt) {
    __shared__ unsigned As[128][36];
    __shared__ unsigned B1s[64][36];
    __shared__ unsigned B2s[64][36];
    const int row0 = blockIdx.y * 128, col0 = blockIdx.x * 64;
    const int tid = threadIdx.x;
    const int lane = tid & 31, w = tid >> 5;
    const int g = lane >> 2, tg = lane & 3;
    const int wm = (w & 3) * 32, wn = (w >> 2) * 32;
    const int ar = tid >> 3, ac = (tid & 7) * 4;

    const float* Ap[4];
    #pragma unroll
    for (int p = 0; p < 4; p++)
        Ap[p] = A + (size_t)(row0 + p*32 + ar) * DD + ac;
    const float* B1p[2]; const float* B2p[2];
    #pragma unroll
    for (int p = 0; p < 2; p++) {
        B1p[p] = B + (size_t)(col0 + p*32 + ar) * DD + ac;
        B2p[p] = B + (size_t)(DSH + col0 + p*32 + ar) * DD + ac;
    }

    #pragma unroll
    for (int p = 0; p < 4; p++) {
        float4 v = *(const float4*)(Ap[p]);
        As[p*32+ar][ac+0]=f2tf32(v.x); As[p*32+ar][ac+1]=f2tf32(v.y);
        As[p*32+ar][ac+2]=f2tf32(v.z); As[p*32+ar][ac+3]=f2tf32(v.w);
    }
    #pragma unroll
    for (int p = 0; p < 2; p++) {
        float4 v1 = *(const float4*)(B1p[p]);
        float4 v2 = *(const float4*)(B2p[p]);
        B1s[p*32+ar][ac+0]=f2tf32(v1.x); B1s[p*32+ar][ac+1]=f2tf32(v1.y);
        B1s[p*32+ar][ac+2]=f2tf32(v1.z); B1s[p*32+ar][ac+3]=f2tf32(v1.w);
        B2s[p*32+ar][ac+0]=f2tf32(v2.x); B2s[p*32+ar][ac+1]=f2tf32(v2.y);
        B2s[p*32+ar][ac+2]=f2tf32(v2.z); B2s[p*32+ar][ac+3]=f2tf32(v2.w);
    }
    __syncthreads();

    float acc1[2][4][4] = {}, acc2[2][4][4] = {};
    float4 pa[4], pb1[2], pb2[2];
    for (int k0 = 0; k0 < DD; k0 += 32) {
        bool nxt = (k0 + 32) < DD;
        if (nxt) {
            #pragma unroll
            for (int p = 0; p < 4; p++) pa[p] = *(const float4*)(Ap[p] + k0 + 32);
            #pragma unroll
            for (int p = 0; p < 2; p++) {
                pb1[p] = *(const float4*)(B1p[p] + k0 + 32);
                pb2[p] = *(const float4*)(B2p[p] + k0 + 32);
            }
        }
        #pragma unroll
        for (int ks = 0; ks < 4; ks++) {
            const int kb = ks*8;
            unsigned af[2][4], bf1[4][2], bf2[4][2];
            #pragma unroll
            for (int i = 0; i < 2; i++) {
                af[i][0] = As[wm+i*16+g  ][kb+tg];
                af[i][1] = As[wm+i*16+8+g][kb+tg];
                af[i][2] = As[wm+i*16+g  ][kb+tg+4];
                af[i][3] = As[wm+i*16+8+g][kb+tg+4];
            }
            #pragma unroll
            for (int j = 0; j < 4; j++) {
                bf1[j][0] = B1s[wn+j*8+g][kb+tg];
                bf1[j][1] = B1s[wn+j*8+g][kb+tg+4];
                bf2[j][0] = B2s[wn+j*8+g][kb+tg];
                bf2[j][1] = B2s[wn+j*8+g][kb+tg+4];
            }
            #pragma unroll
            for (int i = 0; i < 2; i++)
                #pragma unroll
                for (int j = 0; j < 4; j++) {
                    mma8(acc1[i][j], af[i], bf1[j]);
                    mma8(acc2[i][j], af[i], bf2[j]);
                }
        }
        __syncthreads();
        if (nxt) {
            #pragma unroll
            for (int p = 0; p < 4; p++) {
                As[p*32+ar][ac+0]=f2tf32(pa[p].x); As[p*32+ar][ac+1]=f2tf32(pa[p].y);
                As[p*32+ar][ac+2]=f2tf32(pa[p].z); As[p*32+ar][ac+3]=f2tf32(pa[p].w);
            }
            #pragma unroll
            for (int p = 0; p < 2; p++) {
                B1s[p*32+ar][ac+0]=f2tf32(pb1[p].x); B1s[p*32+ar][ac+1]=f2tf32(pb1[p].y);
                B1s[p*32+ar][ac+2]=f2tf32(pb1[p].z); B1s[p*32+ar][ac+3]=f2tf32(pb1[p].w);
                B2s[p*32+ar][ac+0]=f2tf32(pb2[p].x); B2s[p*32+ar][ac+1]=f2tf32(pb2[p].y);
                B2s[p*32+ar][ac+2]=f2tf32(pb2[p].z); B2s[p*32+ar][ac+3]=f2tf32(pb2[p].w);
            }
            __syncthreads();
        }
    }

    #pragma unroll
    for (int i = 0; i < 2; i++) {
        #pragma unroll
        for (int j = 0; j < 4; j++) {
            int r0 = row0 + wm + i*16 + g;
            int cc = col0 + wn + j*8 + tg*2;
            #pragma unroll
            for (int half = 0; half < 2; half++) {
                int r = r0 + half*8;
                float h1a = acc1[i][j][half*2+0], h2a = acc2[i][j][half*2+0];
                float h1b = acc1[i][j][half*2+1], h2b = acc2[i][j][half*2+1];
                float sa = 1.f / (1.f + __expf(-h1a));
                float sb = 1.f / (1.f + __expf(-h1b));
                size_t x = (size_t)r * DSH + cc;
                gt[x]   = h1a * sa * h2a;
                gt[x+1] = h1b * sb * h2b;
            }
        }
    }
}

// ---------------- RoPE (in-place on q,k within qkv buffer) ----------------
__global__ void rope_kernel(float* __restrict__ qkv) {
    int idx = blockIdx.x * blockDim.x + threadIdx.x;
    const int total = 2 * TT * HH * 32;
    if (idx >= total) return;
    int which = idx / (TT * HH * 32);
    int rem   = idx % (TT * HH * 32);
    int t = rem / (HH * 32);
    int r2 = rem % (HH * 32);
    int h = r2 >> 5, i = r2 & 31;
    size_t base = (size_t)t * QKV3 + (size_t)which * DD + h * HDIM;
    float invf = (float)exp(-9.210340371976184 * ((double)i / 32.0));
    float fr = (float)t * invf;
    float c = (float)cos((double)fr);
    float s = (float)sin((double)fr);
    float x1 = qkv[base + i];
    float x2 = qkv[base + 32 + i];
    qkv[base + i]      =  x1 * c + x2 * s;
    qkv[base + 32 + i] = -x1 * s + x2 * c;
}

// =============== flash attention v2: full-row warps, register softmax =====
// 128q x 64k tiles, 256 threads = 8 warps, warp w owns q rows [16w,16w+16).
// Softmax entirely in registers (quad shfl reductions); P never hits smem —
// C-frag -> A-frag conversion for P@V via quad shuffles. Q frags in regs.
#define KSTR 68   // K tile stride (words): QK b-frag loads conflict-free
#define VSTR 72   // V tile stride (words): PV b-frag loads conflict-free
__global__ __launch_bounds__(256) void attn_kernel(const float* __restrict__ qkv,
                                                   float* __restrict__ o) {
    __shared__ unsigned sm[64*KSTR + 64*VSTR];   // 35840 B; Q staged here first
    unsigned* Ks = sm;
    unsigned* Vs = sm + 64*KSTR;

    const int qb = gridDim.x - 1 - blockIdx.x;   // heavy blocks first
    const int h = blockIdx.y;
    const int tid = threadIdx.x;
    const int lane = tid & 31, w = tid >> 5;
    const int g = lane >> 2, tg = lane & 3;
    const bool odd = tg & 1;
    const int s0 = tg >> 1, s1 = 2 + (tg >> 1);

    { // stage Q tile [128][64] as tf32 (stride KSTR)
        int qi = tid >> 1, d0 = (tid & 1) * 32;
        const float* src = qkv + (size_t)(qb*128 + qi) * QKV3 + h * HDIM + d0;
        #pragma unroll
        for (int c = 0; c < 32; c += 4) {
            float4 v = *(const float4*)(src + c);
            sm[qi*KSTR + d0+c+0] = f2tf32(v.x); sm[qi*KSTR + d0+c+1] = f2tf32(v.y);
            sm[qi*KSTR + d0+c+2] = f2tf32(v.z); sm[qi*KSTR + d0+c+3] = f2tf32(v.w);
        }
    }
    __syncthreads();
    unsigned aq[8][4];
    { // Q fragments to registers (warp rows 16w..16w+15)
        int r0 = 16*w + g;
        #pragma unroll
        for (int kk = 0; kk < 8; kk++) {
            aq[kk][0] = sm[(r0  )*KSTR + 8*kk + tg];
            aq[kk][1] = sm[(r0+8)*KSTR + 8*kk + tg];
            aq[kk][2] = sm[(r0  )*KSTR + 8*kk + tg + 4];
            aq[kk][3] = sm[(r0+8)*KSTR + 8*kk + tg + 4];
        }
    }
    __syncthreads();

    float m0 = -INFINITY, m1 = -INFINITY, l0 = 0.f, l1 = 0.f;
    float acco[8][4] = {};
    const int qg0 = qb*128 + 16*w + g;
    const int qg1 = qg0 + 8;
    const int kbmax = 2*qb + 1;

    for (int kb = 0; kb <= kbmax; kb++) {
        { // load K,V tiles as tf32
            int ki = tid >> 2, d0 = (tid & 3) * 16;
            const float* kp = qkv + (size_t)(kb*64 + ki) * QKV3 + DD   + h*HDIM + d0;
            const float* vp = qkv + (size_t)(kb*64 + ki) * QKV3 + 2*DD + h*HDIM + d0;
            #pragma unroll
            for (int c = 0; c < 16; c += 4) {
                float4 kv = *(const float4*)(kp + c);
                Ks[ki*KSTR + d0+c+0]=f2tf32(kv.x); Ks[ki*KSTR + d0+c+1]=f2tf32(kv.y);
                Ks[ki*KSTR + d0+c+2]=f2tf32(kv.z); Ks[ki*KSTR + d0+c+3]=f2tf32(kv.w);
                float4 vv = *(const float4*)(vp + c);
                Vs[ki*VSTR + d0+c+0]=f2tf32(vv.x); Vs[ki*VSTR + d0+c+1]=f2tf32(vv.y);
                Vs[ki*VSTR + d0+c+2]=f2tf32(vv.z); Vs[ki*VSTR + d0+c+3]=f2tf32(vv.w);
            }
        }
        __syncthreads();

        // S = Q @ K^T : warp tile 16 rows x 64 cols (8 n-tiles)
        float sf[8][4] = {};
        #pragma unroll
        for (int kk = 0; kk < 8; kk++) {
            #pragma unroll
            for (int j = 0; j < 8; j++) {
                unsigned b[2] = { Ks[(8*j+g)*KSTR + 8*kk + tg],
                                  Ks[(8*j+g)*KSTR + 8*kk + tg + 4] };
                mma8(sf[j], aq[kk], b);
            }
        }
        // scale + causal mask + register softmax
        float vmax0 = -1e30f, vmax1 = -1e30f;
        #pragma unroll
        for (int j = 0; j < 8; j++) {
            int kg = kb*64 + 8*j + 2*tg;
            sf[j][0] = (kg   > qg0) ? -1e30f : sf[j][0]*0.125f;
            sf[j][1] = (kg+1 > qg0) ? -1e30f : sf[j][1]*0.125f;
            sf[j][2] = (kg   > qg1) ? -1e30f : sf[j][2]*0.125f;
            sf[j][3] = (kg+1 > qg1) ? -1e30f : sf[j][3]*0.125f;
            vmax0 = fmaxf(vmax0, fmaxf(sf[j][0], sf[j][1]));
            vmax1 = fmaxf(vmax1, fmaxf(sf[j][2], sf[j][3]));
        }
        vmax0 = fmaxf(vmax0, __shfl_xor_sync(0xffffffffu, vmax0, 1));
        vmax0 = fmaxf(vmax0, __shfl_xor_sync(0xffffffffu, vmax0, 2));
        vmax1 = fmaxf(vmax1, __shfl_xor_sync(0xffffffffu, vmax1, 1));
        vmax1 = fmaxf(vmax1, __shfl_xor_sync(0xffffffffu, vmax1, 2));
        float mn0 = fmaxf(m0, vmax0), mn1 = fmaxf(m1, vmax1);
        float al0 = __expf(m0 - mn0), al1 = __expf(m1 - mn1);
        float ps0 = 0.f, ps1 = 0.f;
        #pragma unroll
        for (int j = 0; j < 8; j++) {
            sf[j][0] = __expf(sf[j][0] - mn0); ps0 += sf[j][0];
            sf[j][1] = __expf(sf[j][1] - mn0); ps0 += sf[j][1];
            sf[j][2] = __expf(sf[j][2] - mn1); ps1 += sf[j][2];
            sf[j][3] = __expf(sf[j][3] - mn1); ps1 += sf[j][3];
        }
        ps0 += __shfl_xor_sync(0xffffffffu, ps0, 1);
        ps0 += __shfl_xor_sync(0xffffffffu, ps0, 2);
        ps1 += __shfl_xor_sync(0xffffffffu, ps1, 1);
        ps1 += __shfl_xor_sync(0xffffffffu, ps1, 2);
        l0 = l0*al0 + ps0; l1 = l1*al1 + ps1;
        m0 = mn0; m1 = mn1;
        #pragma unroll
        for (int jd = 0; jd < 8; jd++) {
            acco[jd][0] *= al0; acco[jd][1] *= al0;
            acco[jd][2] *= al1; acco[jd][3] *= al1;
        }
        // O += P @ V : A-frags built from C-frags via quad shuffles
        #pragma unroll
        for (int j = 0; j < 8; j++) {
            float q00 = __shfl_sync(0xffffffffu, sf[j][0], s0, 4);
            float q01 = __shfl_sync(0xffffffffu, sf[j][1], s0, 4);
            float q10 = __shfl_sync(0xffffffffu, sf[j][2], s0, 4);
            float q11 = __shfl_sync(0xffffffffu, sf[j][3], s0, 4);
            float r00 = __shfl_sync(0xffffffffu, sf[j][0], s1, 4);
            float r01 = __shfl_sync(0xffffffffu, sf[j][1], s1, 4);
            float r10 = __shfl_sync(0xffffffffu, sf[j][2], s1, 4);
            float r11 = __shfl_sync(0xffffffffu, sf[j][3], s1, 4);
            unsigned a[4];
            a[0] = f2tf32(odd ? q01 : q00);   // P[g   ][8j+tg]
            a[1] = f2tf32(odd ? q11 : q10);   // P[g+8 ][8j+tg]
            a[2] = f2tf32(odd ? r01 : r00);   // P[g   ][8j+tg+4]
            a[3] = f2tf32(odd ? r11 : r10);   // P[g+8 ][8j+tg+4]
            #pragma unroll
            for (int jd = 0; jd < 8; jd++) {
                unsigned b[2] = { Vs[(8*j+tg  )*VSTR + 8*jd + g],
                                  Vs[(8*j+tg+4)*VSTR + 8*jd + g] };
                mma8(acco[jd], a, b);
            }
        }
        __syncthreads();
    }

    // epilogue: divide by l and store
    float i0 = 1.f / l0, i1 = 1.f / l1;
    #pragma unroll
    for (int jd = 0; jd < 8; jd++) {
        int col = h*HDIM + 8*jd + 2*tg;
        o[(size_t)qg0*DD + col  ] = acco[jd][0]*i0;
        o[(size_t)qg0*DD + col+1] = acco[jd][1]*i0;
        o[(size_t)qg1*DD + col  ] = acco[jd][2]*i1;
        o[(size_t)qg1*DD + col+1] = acco[jd][3]*i1;
    }
}

// ---------------- router ----------------
__global__ void router_kernel(const float* __restrict__ xffn, const float* __restrict__ mk,
                              const float* __restrict__ bias, const int* __restrict__ indices,
                              const float* __restrict__ values, float* __restrict__ scores) {
    int t = blockIdx.x;
    __shared__ float red[128 * NEXP];
    float partial[NEXP];
    #pragma unroll
    for (int e = 0; e < NEXP; e++) partial[e] = 0.f;
    for (int d = threadIdx.x; d < DD; d += 128) {
        float xv = xffn[(size_t)t*DD + d];
        const float* mrow = mk + (size_t)d * NEXP;
        #pragma unroll
        for (int e = 0; e < NEXP; e++) partial[e] += xv * mrow[e];
    }
    #pragma unroll
    for (int e = 0; e < NEXP; e++) red[threadIdx.x*NEXP + e] = partial[e];
    __syncthreads();
    for (int s = 64; s >= 1; s >>= 1) {
        if (threadIdx.x < s)
            #pragma unroll
            for (int e = 0; e < NEXP; e++)
                red[threadIdx.x*NEXP + e] += red[(threadIdx.x+s)*NEXP + e];
        __syncthreads();
    }
    if (threadIdx.x == 0) {
        int i0 = indices[t*2+0], i1 = indices[t*2+1];
        float v0 = values[t*2+0] + red[i0] + bias[i0];
        float v1 = values[t*2+1] + red[i1] + bias[i1];
        float m = fmaxf(v0, v1);
        float e0 = __expf(v0 - m), e1 = __expf(v1 - m);
        float inv = 1.f / (e0 + e1);
        scores[t*2+0] = e0 * inv;
        scores[t*2+1] = e1 * inv;
    }
}

// ---------------- routing build ----------------
__global__ void route_init(int* counts) { if (threadIdx.x < NEXP) counts[threadIdx.x] = 0; }
__global__ void route_count(const int* __restrict__ indices, int* counts) {
    int i = blockIdx.x * blockDim.x + threadIdx.x;
    if (i < TT*TOPK) atomicAdd(&counts[indices[i]], 1);
}
__global__ void route_scan(const int* __restrict__ counts, int* offsets, int* cursor) {
    if (threadIdx.x == 0) {
        int off = 0;
        for (int e = 0; e < NEXP; e++) { offsets[e] = off; cursor[e] = off; off += counts[e]; }
        offsets[NEXP] = off;
    }
}
__global__ void route_scatter(const int* __restrict__ indices, int* cursor,
                              int* __restrict__ perm, int* __restrict__ slotpos) {
    int i = blockIdx.x * blockDim.x + threadIdx.x;
    if (i < TT*TOPK) {
        int e = indices[i];
        int p = atomicAdd(&cursor[e], 1);
        perm[p] = i >> 1;
        slotpos[i] = p;
    }
}

// =============== expert up (tf32): g = silu(x@W1) * (x@W2), gathered A ====
__global__ __launch_bounds__(256) void expert_up_tf32(
        const float* __restrict__ xffn, const float* __restrict__ experts,
        const int* __restrict__ counts, const int* __restrict__ offsets,
        const int* __restrict__ perm, float* __restrict__ g_out) {
    const int e = blockIdx.z;
    const int M = counts[e];
    const int row0 = blockIdx.y * 64;
    if (row0 >= M) return;
    const int off = offsets[e];
    const float* B1 = experts + (size_t)e * DD * EDIM;
    const float* B2 = experts + ((size_t)NEXP + e) * DD * EDIM;
    const int col0 = blockIdx.x * 64;

    __shared__ unsigned As[64][36];
    __shared__ unsigned B1s[32][72];
    __shared__ unsigned B2s[32][72];

    const int tid = threadIdx.x;
    const int lane = tid & 31, w = tid >> 5;
    const int g = lane >> 2, tg = lane & 3;
    const int wm = (w & 1) * 32, wn = (w >> 1) * 16;
    const int ar = tid >> 3, ac = (tid & 7) * 4;
    const int bkr = tid >> 4, bnc = (tid & 15) * 4;

    const float* Ap[2]; bool va[2];
    #pragma unroll
    for (int p = 0; p < 2; p++) {
        int r = row0 + p*32 + ar;
        va[p] = r < M;
        int tok = va[p] ? perm[off + r] : 0;
        Ap[p] = xffn + (size_t)tok * DD + ac;
    }
    const float* B1p[2]; const float* B2p[2];
    #pragma unroll
    for (int p = 0; p < 2; p++) {
        B1p[p] = B1 + (size_t)(p*16 + bkr) * EDIM + col0 + bnc;
        B2p[p] = B2 + (size_t)(p*16 + bkr) * EDIM + col0 + bnc;
    }

    #pragma unroll
    for (int p = 0; p < 2; p++) {
        float4 v = va[p] ? *(const float4*)(Ap[p]) : make_float4(0,0,0,0);
        As[p*32+ar][ac+0]=f2tf32(v.x); As[p*32+ar][ac+1]=f2tf32(v.y);
        As[p*32+ar][ac+2]=f2tf32(v.z); As[p*32+ar][ac+3]=f2tf32(v.w);
    }
    #pragma unroll
    for (int p = 0; p < 2; p++) {
        float4 v1 = *(const float4*)(B1p[p]);
        float4 v2 = *(const float4*)(B2p[p]);
        B1s[p*16+bkr][bnc+0]=f2tf32(v1.x); B1s[p*16+bkr][bnc+1]=f2tf32(v1.y);
        B1s[p*16+bkr][bnc+2]=f2tf32(v1.z); B1s[p*16+bkr][bnc+3]=f2tf32(v1.w);
        B2s[p*16+bkr][bnc+0]=f2tf32(v2.x); B2s[p*16+bkr][bnc+1]=f2tf32(v2.y);
        B2s[p*16+bkr][bnc+2]=f2tf32(v2.z); B2s[p*16+bkr][bnc+3]=f2tf32(v2.w);
    }
    __syncthreads();

    float acc1[2][2][4] = {}, acc2[2][2][4] = {};
    float4 pa[2], pb1[2], pb2[2];
    for (int k0 = 0; k0 < DD; k0 += 32) {
        bool nxt = (k0 + 32) < DD;
        if (nxt) {
            #pragma unroll
            for (int p = 0; p < 2; p++)
                pa[p] = va[p] ? *(const float4*)(Ap[p] + k0 + 32) : make_float4(0,0,0,0);
            #pragma unroll
            for (int p = 0; p < 2; p++) {
                pb1[p] = *(const float4*)(B1p[p] + (size_t)(k0 + 32) * EDIM);
                pb2[p] = *(const float4*)(B2p[p] + (size_t)(k0 + 32) * EDIM);
            }
        }
        #pragma unroll
        for (int ks = 0; ks < 4; ks++) {
            const int kb = ks*8;
            unsigned af[2][4], bf1[2][2], bf2[2][2];
            #pragma unroll
            for (int i = 0; i < 2; i++) {
                af[i][0] = As[wm+i*16+g  ][kb+tg];
                af[i][1] = As[wm+i*16+8+g][kb+tg];
                af[i][2] = As[wm+i*16+g  ][kb+tg+4];
                af[i][3] = As[wm+i*16+8+g][kb+tg+4];
            }
            #pragma unroll
            for (int j = 0; j < 2; j++) {
                bf1[j][0] = B1s[kb+tg  ][wn+j*8+g];
                bf1[j][1] = B1s[kb+tg+4][wn+j*8+g];
                bf2[j][0] = B2s[kb+tg  ][wn+j*8+g];
                bf2[j][1] = B2s[kb+tg+4][wn+j*8+g];
            }
            #pragma unroll
            for (int i = 0; i < 2; i++)
                #pragma unroll
                for (int j = 0; j < 2; j++) {
                    mma8(acc1[i][j], af[i], bf1[j]);
                    mma8(acc2[i][j], af[i], bf2[j]);
                }
        }
        __syncthreads();
        if (nxt) {
            #pragma unroll
            for (int p = 0; p < 2; p++) {
                As[p*32+ar][ac+0]=f2tf32(pa[p].x); As[p*32+ar][ac+1]=f2tf32(pa[p].y);
                As[p*32+ar][ac+2]=f2tf32(pa[p].z); As[p*32+ar][ac+3]=f2tf32(pa[p].w);
            }
            #pragma unroll
            for (int p = 0; p < 2; p++) {
                B1s[p*16+bkr][bnc+0]=f2tf32(pb1[p].x); B1s[p*16+bkr][bnc+1]=f2tf32(pb1[p].y);
                B1s[p*16+bkr][bnc+2]=f2tf32(pb1[p].z); B1s[p*16+bkr][bnc+3]=f2tf32(pb1[p].w);
                B2s[p*16+bkr][bnc+0]=f2tf32(pb2[p].x); B2s[p*16+bkr][bnc+1]=f2tf32(pb2[p].y);
                B2s[p*16+bkr][bnc+2]=f2tf32(pb2[p].z); B2s[p*16+bkr][bnc+3]=f2tf32(pb2[p].w);
            }
            __syncthreads();
        }
    }

    #pragma unroll
    for (int i = 0; i < 2; i++) {
        #pragma unroll
        for (int j = 0; j < 2; j++) {
            int r0 = row0 + wm + i*16 + g;
            int cc = col0 + wn + j*8 + tg*2;
            #pragma unroll
            for (int half = 0; half < 2; half++) {
                int r = r0 + half*8;
                if (r < M) {
                    float h1a = acc1[i][j][half*2+0], h2a = acc2[i][j][half*2+0];
                    float h1b = acc1[i][j][half*2+1], h2b = acc2[i][j][half*2+1];
                    float sa = 1.f / (1.f + __expf(-h1a));
                    float sb = 1.f / (1.f + __expf(-h1b));
                    size_t x = (size_t)(off + r) * EDIM + cc;
                    g_out[x]   = h1a * sa * h2a;
                    g_out[x+1] = h1b * sb * h2b;
                }
            }
        }
    }
}

// =============== expert down (tf32 NT): yp = g @ W3^T, per-expert slabs ===
__global__ __launch_bounds__(256) void expert_down_tf32(
        const float* __restrict__ gbuf, const float* __restrict__ experts,
        const int* __restrict__ counts, const int* __restrict__ offsets,
        float* __restrict__ yp) {
    const int e = blockIdx.z;
    const int M = counts[e];
    const int row0 = blockIdx.y * 128;
    if (row0 >= M) return;
    const int off = offsets[e];
    __shared__ SmemNT s;
    gemm_nt_body(s,
                 gbuf + (size_t)off * EDIM,
                 experts + (2*(size_t)NEXP + e) * DD * EDIM,
                 nullptr,
                 yp + (size_t)off * DD,
                 M, DD, EDIM, row0, blockIdx.x * 128);
}

// ---------------- combine experts (scores * yp) * coeff -------------------
__global__ void combine_kernel(const float* __restrict__ yp, const float* __restrict__ scores,
                               const int* __restrict__ slotpos, const float* __restrict__ coeff,
                               float* __restrict__ ycomb) {
    int t = blockIdx.x;
    float s0 = scores[t*2+0], s1 = scores[t*2+1];
    int p0 = slotpos[t*2+0], p1 = slotpos[t*2+1];
    const float* r0 = yp + (size_t)p0 * DD;
    const float* r1 = yp + (size_t)p1 * DD;
    #pragma unroll
    for (int i = 0; i < 4; i++) {
        int d = threadIdx.x + i*256;
        ycomb[(size_t)t*DD + d] = (s0*r0[d] + s1*r1[d]) * coeff[d];
    }
}

// ---------------- final: out = ycomb + rmsnorm(ysh)*w + x_ffn_input ------
__global__ void final_kernel(const float* __restrict__ ycomb, const float* __restrict__ ysh,
                             const float* __restrict__ shw, const float* __restrict__ xfi,
                             float* __restrict__ out) {
    int t = blockIdx.x;
    const float* yr = ysh + (size_t)t * DD;
    float v[4]; float s = 0.f;
    #pragma unroll
    for (int i = 0; i < 4; i++) { v[i] = yr[threadIdx.x + i*256]; s += v[i]*v[i]; }
    __shared__ float red[8];
    #pragma unroll
    for (int off = 16; off > 0; off >>= 1) s += __shfl_xor_sync(0xffffffffu, s, off);
    if ((threadIdx.x & 31) == 0) red[threadIdx.x >> 5] = s;
    __syncthreads();
    if (threadIdx.x == 0) {
        float tot = 0.f;
        #pragma unroll
        for (int i = 0; i < 8; i++) tot += red[i];
        red[0] = tot;
    }
    __syncthreads();
    float sc = rsqrtf(red[0] / (float)DD + 1e-5f);
    #pragma unroll
    for (int i = 0; i < 4; i++) {
        int d = threadIdx.x + i*256;
        size_t idx = (size_t)t*DD + d;
        out[idx] = ycomb[idx] + v[i]*sc*shw[d] + xfi[idx];
    }
}

// ---------------- launch ----------------
extern "C" void kernel_launch(void* const* d_in, const int* in_sizes, int n_in,
                              void* d_out, int out_size) {
    const float* x_input     = (const float*)d_in[0];
    const int*   indices     = (const int*)  d_in[1];
    const float* values      = (const float*)d_in[2];
    const float* attn_w      = (const float*)d_in[3];
    const float* attn_o_w    = (const float*)d_in[4];
    const float* attn_norm_w = (const float*)d_in[5];
    const float* ffn_norm_w  = (const float*)d_in[6];
    const float* ffn_experts = (const float*)d_in[7];
    const float* main_keys   = (const float*)d_in[8];
    const float* main_bias   = (const float*)d_in[9];
    const float* out_coeff   = (const float*)d_in[10];
    const float* ffn_up_w    = (const float*)d_in[11];
    const float* ffn_down_w  = (const float*)d_in[12];
    const float* shared_nw   = (const float*)d_in[13];
    float* out = (float*)d_out;

    float* bufF = nullptr; int* bufI = nullptr;
    cudaGetSymbolAddress((void**)&bufF, g_bufF);
    cudaGetSymbolAddress((void**)&bufI, g_bufI);

    float* xn   = bufF + OFF_XN;
    float* qkv  = bufF + OFF_QKV;
    float* ao   = bufF + OFF_AO;
    float* xfi  = bufF + OFF_XFI;
    float* xfn  = bufF + OFF_XFN;
    float* sc   = bufF + OFF_SC;
    float* gbuf = bufF + OFF_G;
    float* yp   = bufF + OFF_YP;
    float* yc   = bufF + OFF_YC;
    float* gt   = bufF + OFF_GT;
    float* ys   = bufF + OFF_YS;

    int* cnt  = bufI + IOFF_CNT;
    int* offs = bufI + IOFF_OFFS;
    int* cur  = bufI + IOFF_CUR;
    int* perm = bufI + IOFF_PERM;
    int* slot = bufI + IOFF_SLOT;

    // 1. attention pre-norm
    rmsnorm_kernel<<<TT, 256>>>(x_input, attn_norm_w, xn);
    // 2. QKV (tf32 tensor, 128x128 tiles)
    gemm_tf32_nt<<<dim3(QKV3/128, TT/128), 256>>>(xn, attn_w, nullptr, qkv, TT, QKV3, DD);
    // 3. RoPE on q,k
    rope_kernel<<<(2*TT*HH*32 + 255)/256, 256>>>(qkv);
    // 4. attention (tf32 tensor, register softmax)
    attn_kernel<<<dim3(TT/128, HH), 256>>>(qkv, ao);
    // 5. O proj + residual (tf32)
    gemm_tf32_nt<<<dim3(DD/128, TT/128), 256>>>(ao, attn_o_w, x_input, xfi, TT, DD, DD);
    // 6. ffn pre-norm
    rmsnorm_kernel<<<TT, 256>>>(xfi, ffn_norm_w, xfn);
    // 7. router scores
    router_kernel<<<TT, 128>>>(xfn, main_keys, main_bias, indices, values, sc);
    // 8. routing permutation
    route_init<<<1, 32>>>(cnt);
    route_count<<<(TT*TOPK + 255)/256, 256>>>(indices, cnt);
    route_scan<<<1, 32>>>(cnt, offs, cur);
    route_scatter<<<(TT*TOPK + 255)/256, 256>>>(indices, cur, perm, slot);
    // 9. expert up (tf32 dual GEMM + SiLU)
    expert_up_tf32<<<dim3(EDIM/64, (TT*TOPK)/64, NEXP), 256>>>(xfn, ffn_experts, cnt, offs, perm, gbuf);
    // 10. expert down (tf32, 128x128 tiles)
    expert_down_tf32<<<dim3(DD/128, (TT*TOPK)/128, NEXP), 256>>>(gbuf, ffn_experts, cnt, offs, yp);
    // 11. combine
    combine_kernel<<<TT, 256>>>(yp, sc, slot, out_coeff, yc);
    // 12. shared expert up + gate (fused dual-B tf32)
    shared_up_gate_tf32<<<dim3(DSH/64, TT/128), 256>>>(xfn, ffn_up_w, gt);
    // 13. shared expert down (tf32)
    gemm_tf32_nt<<<dim3(DD/128, TT/128), 256>>>(gt, ffn_down_w, nullptr, ys, TT, DD, DSH);
    // 14. final combine
    final_kernel<<<TT, 256>>>(yc, ys, shared_nw, xfi, out);
}